// round 2
// baseline (speedup 1.0000x reference)
#include <cuda_runtime.h>
#include <cstddef>

#define NMAX 50048
#define EMAX 800000
#define H 256
#define HH (H*H)

// ---------------- scratch (static device globals; no allocation) ----------------
__device__ __align__(16) float g_P0[(size_t)NMAX*H];
__device__ __align__(16) float g_P1[(size_t)NMAX*H];
__device__ __align__(16) float g_P2[(size_t)NMAX*H];
__device__ __align__(16) float g_ACCA[(size_t)NMAX*H];
__device__ __align__(16) float g_ACCB[(size_t)NMAX*H];
__device__ __align__(16) float g_HA[(size_t)NMAX*H];
__device__ __align__(16) float g_HB[(size_t)NMAX*H];

__device__ int g_cnt[3][NMAX];
__device__ int g_rowptr[3][NMAX+1];
__device__ int g_cursor[3][NMAX];
__device__ int g_col[3][EMAX];

// 0 CSRC_AB1, 1 CSRC_BA1, 2 CSRC_AA1, 3 CDST_B1, 4 CDST_A1,
// 5 CSRC_AB2, 6 CSRC_BA2, 7 CSRC_AA2, 8 CDST_B2, 9 CDST_A2
__device__ __align__(16) float g_CW[10][HH];
__device__ __align__(16) float g_bias[4][H];   // BIAS_B1, BIAS_A1, BIAS_B2, BIAS_A2
__device__ __align__(16) float g_bnsum[1024];  // [sumA, sqA, sumB, sqB] x 256
__device__ __align__(16) float g_bnss[1024];   // [scaleA, shiftA, scaleB, shiftB] x 256

// ---------------- tiny utility kernels ----------------
__global__ void zero_int_kernel(int* p, int n) {
    int i = blockIdx.x * blockDim.x + threadIdx.x;
    if (i < n) p[i] = 0;
}
__global__ void zero_float_kernel(float* p, int n) {
    int i = blockIdx.x * blockDim.x + threadIdx.x;
    if (i < n) p[i] = 0.f;
}
__global__ void copy_int_kernel(int* dst, const int* src, int n) {
    int i = blockIdx.x * blockDim.x + threadIdx.x;
    if (i < n) dst[i] = src[i];
}

// ---------------- CSR build ----------------
__global__ void count_kernel(const int* __restrict__ dst, int E, int* __restrict__ cnt) {
    int e = blockIdx.x * blockDim.x + threadIdx.x;
    if (e < E) atomicAdd(&cnt[dst[e]], 1);
}

__global__ void scan_kernel(const int* __restrict__ cnt, int* __restrict__ rowptr, int n) {
    __shared__ int buf[1024];
    __shared__ int carry;
    int t = threadIdx.x;
    if (t == 0) carry = 0;
    __syncthreads();
    for (int base = 0; base < n; base += 1024) {
        int i = base + t;
        int v = (i < n) ? cnt[i] : 0;
        buf[t] = v;
        __syncthreads();
        for (int off = 1; off < 1024; off <<= 1) {
            int add = (t >= off) ? buf[t - off] : 0;
            __syncthreads();
            buf[t] += add;
            __syncthreads();
        }
        int incl = buf[t];
        int c = carry;
        if (i < n) rowptr[i] = c + incl - v;  // exclusive
        __syncthreads();
        if (t == 1023) carry = c + buf[1023];
        __syncthreads();
    }
    if (t == 0) rowptr[n] = carry;
}

__global__ void fill_kernel(const int* __restrict__ src, const int* __restrict__ dst,
                            int E, int* __restrict__ cur, int* __restrict__ col) {
    int e = blockIdx.x * blockDim.x + threadIdx.x;
    if (e < E) {
        int p = atomicAdd(&cur[dst[e]], 1);
        col[p] = src[e];
    }
}

// ---------------- combined-weight precompute ----------------
// C[h, 0:D] (+)= scale * sum_j Wupd[h, colOff+j] * W[j, 0:D]
__global__ void combine_w_kernel(float* __restrict__ C, const float* __restrict__ Wupd, int colOff,
                                 const float* __restrict__ W, int D, float scale, int accum) {
    int d4 = blockIdx.x * blockDim.x + threadIdx.x;  // float4 column index
    int h = blockIdx.y;
    if (d4 >= D / 4) return;
    const float* wrow = Wupd + (size_t)h * 512 + colOff;
    float4 acc = make_float4(0.f, 0.f, 0.f, 0.f);
#pragma unroll 8
    for (int j = 0; j < 256; j++) {
        float u = wrow[j];
        float4 w = *(const float4*)(W + (size_t)j * D + d4 * 4);
        acc.x += u * w.x; acc.y += u * w.y; acc.z += u * w.z; acc.w += u * w.w;
    }
    float4* out = (float4*)(C + (size_t)h * D) + d4;
    float4 r;
    if (accum) {
        r = *out;
        r.x += scale * acc.x; r.y += scale * acc.y; r.z += scale * acc.z; r.w += scale * acc.w;
    } else {
        r.x = scale * acc.x; r.y = scale * acc.y; r.z = scale * acc.z; r.w = scale * acc.w;
    }
    *out = r;
}

// out[h] (+)= scale * ( sum_j Wupd[h,j]*bdst[j] + Wupd[h,256+j]*bsrc[j] + bupd[h] )
__global__ void combine_b_kernel(float* __restrict__ out, const float* __restrict__ Wupd,
                                 const float* __restrict__ bdst, const float* __restrict__ bsrc,
                                 const float* __restrict__ bupd, float scale, int accum) {
    int h = threadIdx.x;
    const float* r = Wupd + (size_t)h * 512;
    float acc = bupd[h];
#pragma unroll 8
    for (int j = 0; j < 256; j++) acc += r[j] * bdst[j] + r[256 + j] * bsrc[j];
    float v = scale * acc;
    if (accum) out[h] += v; else out[h] = v;
}

// ---------------- fp32 SGEMM: C[M,256] = A[M,K] @ B[256,K]^T (+bias) ----------------
__global__ __launch_bounds__(256) void sgemm_nt(const float* __restrict__ A, const float* __restrict__ B,
                                                const float* __restrict__ bias, float* __restrict__ C,
                                                int M, int K) {
    __shared__ float As[8][128];
    __shared__ float Bs[8][128];
    int tid = threadIdx.x;
    int m0 = blockIdx.x * 128;
    int n0 = blockIdx.y * 128;
    int lr = tid >> 1;
    int lk = (tid & 1) * 4;
    int tx = tid & 15;
    int ty = tid >> 4;
    float acc[8][8];
#pragma unroll
    for (int i = 0; i < 8; i++)
#pragma unroll
        for (int j = 0; j < 8; j++) acc[i][j] = 0.f;

    for (int k0 = 0; k0 < K; k0 += 8) {
        float4 a4 = make_float4(0.f, 0.f, 0.f, 0.f);
        int ar = m0 + lr;
        if (ar < M) a4 = *(const float4*)(A + (size_t)ar * K + k0 + lk);
        float4 b4 = *(const float4*)(B + (size_t)(n0 + lr) * K + k0 + lk);
        As[lk + 0][lr] = a4.x; As[lk + 1][lr] = a4.y; As[lk + 2][lr] = a4.z; As[lk + 3][lr] = a4.w;
        Bs[lk + 0][lr] = b4.x; Bs[lk + 1][lr] = b4.y; Bs[lk + 2][lr] = b4.z; Bs[lk + 3][lr] = b4.w;
        __syncthreads();
#pragma unroll
        for (int kk = 0; kk < 8; kk++) {
            float a[8], b[8];
            *(float4*)(a)     = *(const float4*)&As[kk][ty * 8];
            *(float4*)(a + 4) = *(const float4*)&As[kk][ty * 8 + 4];
            *(float4*)(b)     = *(const float4*)&Bs[kk][tx * 8];
            *(float4*)(b + 4) = *(const float4*)&Bs[kk][tx * 8 + 4];
#pragma unroll
            for (int i = 0; i < 8; i++)
#pragma unroll
                for (int j = 0; j < 8; j++) acc[i][j] += a[i] * b[j];
        }
        __syncthreads();
    }

    float bv[8];
#pragma unroll
    for (int j = 0; j < 8; j++) bv[j] = bias ? bias[n0 + tx * 8 + j] : 0.f;
#pragma unroll
    for (int i = 0; i < 8; i++) {
        int row = m0 + ty * 8 + i;
        if (row < M) {
            float4 v0, v1;
            v0.x = acc[i][0] + bv[0]; v0.y = acc[i][1] + bv[1];
            v0.z = acc[i][2] + bv[2]; v0.w = acc[i][3] + bv[3];
            v1.x = acc[i][4] + bv[4]; v1.y = acc[i][5] + bv[5];
            v1.z = acc[i][6] + bv[6]; v1.w = acc[i][7] + bv[7];
            *(float4*)(C + (size_t)row * 256 + n0 + tx * 8)     = v0;
            *(float4*)(C + (size_t)row * 256 + n0 + tx * 8 + 4) = v1;
        }
    }
}

// ---------------- CSR gather-mean: acc[node] += coef/deg * sum_{e in row} P[col[e]] ----------------
__global__ void gather_kernel(float* __restrict__ acc, const float* __restrict__ P,
                              const int* __restrict__ rowptr, const int* __restrict__ col, float coef) {
    int node = blockIdx.x;
    int start = rowptr[node];
    int end = rowptr[node + 1];
    int deg = end - start;
    if (deg == 0) return;
    int t = threadIdx.x;  // 64 threads, each 4 features (float4)
    float4 s = make_float4(0.f, 0.f, 0.f, 0.f);
    int e = start;
    for (; e + 4 <= end; e += 4) {
        int s0 = col[e], s1 = col[e + 1], s2 = col[e + 2], s3 = col[e + 3];
        float4 v0 = ((const float4*)(P + (size_t)s0 * 256))[t];
        float4 v1 = ((const float4*)(P + (size_t)s1 * 256))[t];
        float4 v2 = ((const float4*)(P + (size_t)s2 * 256))[t];
        float4 v3 = ((const float4*)(P + (size_t)s3 * 256))[t];
        s.x += v0.x + v1.x + v2.x + v3.x;
        s.y += v0.y + v1.y + v2.y + v3.y;
        s.z += v0.z + v1.z + v2.z + v3.z;
        s.w += v0.w + v1.w + v2.w + v3.w;
    }
    for (; e < end; e++) {
        int si = col[e];
        float4 v = ((const float4*)(P + (size_t)si * 256))[t];
        s.x += v.x; s.y += v.y; s.z += v.z; s.w += v.w;
    }
    float scale = coef / (float)deg;
    float4* o = ((float4*)(acc + (size_t)node * 256)) + t;
    float4 cur = *o;
    cur.x += scale * s.x; cur.y += scale * s.y; cur.z += scale * s.z; cur.w += scale * s.w;
    *o = cur;
}

// ---------------- BatchNorm (training stats) + LeakyReLU ----------------
__global__ void bn_stats_kernel(const float* __restrict__ X, int nrows, float* __restrict__ sums) {
    int t = threadIdx.x;  // 256 = feature
    float s = 0.f, q = 0.f;
    for (int r = blockIdx.x; r < nrows; r += gridDim.x) {
        float v = X[(size_t)r * 256 + t];
        s += v;
        q += v * v;
    }
    atomicAdd(&sums[t], s);
    atomicAdd(&sums[256 + t], q);
}

__global__ void bn_pre_kernel(const float* __restrict__ sums, const float* __restrict__ g,
                              const float* __restrict__ b, float* __restrict__ ss, int n) {
    int t = threadIdx.x;
    float fn = (float)n;
    float mean = sums[t] / fn;
    float var = sums[256 + t] / fn - mean * mean;
    float inv = rsqrtf(var + 1e-5f);
    float sc = g[t] * inv;
    ss[t] = sc;
    ss[256 + t] = b[t] - mean * sc;
}

__global__ void bn_apply_kernel(const float* __restrict__ X, const float* __restrict__ ss,
                                float* __restrict__ Y, int n4) {
    int i = blockIdx.x * blockDim.x + threadIdx.x;
    if (i >= n4) return;
    float4 x = ((const float4*)X)[i];
    int t4 = i & 63;
    float4 sc = ((const float4*)ss)[t4];
    float4 sh = ((const float4*)ss)[64 + t4];
    float4 y;
    y.x = x.x * sc.x + sh.x; y.x = y.x > 0.f ? y.x : 0.01f * y.x;
    y.y = x.y * sc.y + sh.y; y.y = y.y > 0.f ? y.y : 0.01f * y.y;
    y.z = x.z * sc.z + sh.z; y.z = y.z > 0.f ? y.z : 0.01f * y.z;
    y.w = x.w * sc.w + sh.w; y.w = y.w > 0.f ? y.w : 0.01f * y.w;
    ((float4*)Y)[i] = y;
}

// ---------------- launcher ----------------
extern "C" void kernel_launch(void* const* d_in, const int* in_sizes, int n_in,
                              void* d_out, int out_size) {
    const float* xA = (const float*)d_in[0];
    const float* xB = (const float*)d_in[1];
    const int* eAB = (const int*)d_in[2];
    const int* eBA = (const int*)d_in[3];
    const int* eAA = (const int*)d_in[4];
    const float* bn_g = (const float*)d_in[29];
    const float* bn_b = (const float*)d_in[30];
    int Nn = in_sizes[0] / 256;
    int E = in_sizes[2] / 2;

    float *P0, *P1, *P2, *ACCA, *ACCB, *HA, *HB, *CW, *BIAS, *BNSUM, *BNSS;
    int *CNT, *ROWPTR, *CURSOR, *COL;
    cudaGetSymbolAddress((void**)&P0, g_P0);
    cudaGetSymbolAddress((void**)&P1, g_P1);
    cudaGetSymbolAddress((void**)&P2, g_P2);
    cudaGetSymbolAddress((void**)&ACCA, g_ACCA);
    cudaGetSymbolAddress((void**)&ACCB, g_ACCB);
    cudaGetSymbolAddress((void**)&HA, g_HA);
    cudaGetSymbolAddress((void**)&HB, g_HB);
    cudaGetSymbolAddress((void**)&CW, g_CW);
    cudaGetSymbolAddress((void**)&BIAS, g_bias);
    cudaGetSymbolAddress((void**)&BNSUM, g_bnsum);
    cudaGetSymbolAddress((void**)&BNSS, g_bnss);
    cudaGetSymbolAddress((void**)&CNT, g_cnt);
    cudaGetSymbolAddress((void**)&ROWPTR, g_rowptr);
    cudaGetSymbolAddress((void**)&CURSOR, g_cursor);
    cudaGetSymbolAddress((void**)&COL, g_col);

    // ---- CSR build (3 edge types, reused by both layers) ----
    const int* edges[3] = {eAB, eBA, eAA};
    int gN = (Nn + 255) / 256;
    int gE = (E + 255) / 256;
    for (int ty = 0; ty < 3; ty++) {
        int* cnt = CNT + ty * NMAX;
        int* rp = ROWPTR + ty * (NMAX + 1);
        int* cur = CURSOR + ty * NMAX;
        int* col = COL + ty * EMAX;
        const int* src = edges[ty];
        const int* dst = edges[ty] + E;
        zero_int_kernel<<<gN, 256>>>(cnt, Nn);
        count_kernel<<<gE, 256>>>(dst, E, cnt);
        scan_kernel<<<1, 1024>>>(cnt, rp, Nn);
        copy_int_kernel<<<gN, 256>>>(cur, rp, Nn);
        fill_kernel<<<gE, 256>>>(src, dst, E, cur, col);
    }

    // ---- combined weights ----
    const float* f5 = (const float*)d_in[5];   const float* f6 = (const float*)d_in[6];
    const float* f7 = (const float*)d_in[7];   const float* f8 = (const float*)d_in[8];
    const float* f9 = (const float*)d_in[9];   const float* f10 = (const float*)d_in[10];
    const float* f11 = (const float*)d_in[11]; const float* f12 = (const float*)d_in[12];
    const float* f13 = (const float*)d_in[13]; const float* f14 = (const float*)d_in[14];
    const float* f15 = (const float*)d_in[15]; const float* f16 = (const float*)d_in[16];
    const float* f17 = (const float*)d_in[17]; const float* f18 = (const float*)d_in[18];
    const float* f19 = (const float*)d_in[19]; const float* f20 = (const float*)d_in[20];
    const float* f21 = (const float*)d_in[21]; const float* f22 = (const float*)d_in[22];
    const float* Ws2 = (const float*)d_in[23]; const float* bs2 = (const float*)d_in[24];
    const float* Wd2 = (const float*)d_in[25]; const float* bd2 = (const float*)d_in[26];
    const float* Wu2 = (const float*)d_in[27]; const float* bu2 = (const float*)d_in[28];

    dim3 cb64(1, 256), cb32(1, 256);
    // layer 1
    combine_w_kernel<<<cb64, 64>>>(CW + 0 * HH, f9, 256, f5, 256, 1.f, 0);     // CSRC_AB1
    combine_w_kernel<<<cb32, 32>>>(CW + 1 * HH, f15, 256, f11, 128, 1.f, 0);   // CSRC_BA1
    combine_w_kernel<<<cb64, 64>>>(CW + 2 * HH, f21, 256, f17, 256, 1.f, 0);   // CSRC_AA1
    combine_w_kernel<<<cb32, 32>>>(CW + 3 * HH, f9, 0, f7, 128, 1.f, 0);       // CDST_B1
    combine_w_kernel<<<cb64, 64>>>(CW + 4 * HH, f15, 0, f13, 256, 0.5f, 0);    // CDST_A1 (ba)
    combine_w_kernel<<<cb64, 64>>>(CW + 4 * HH, f21, 0, f19, 256, 0.5f, 1);    //   += aa
    combine_b_kernel<<<1, 256>>>(BIAS + 0 * H, f9, f8, f6, f10, 1.f, 0);       // BIAS_B1
    combine_b_kernel<<<1, 256>>>(BIAS + 1 * H, f15, f14, f12, f16, 0.5f, 0);   // BIAS_A1 (ba)
    combine_b_kernel<<<1, 256>>>(BIAS + 1 * H, f21, f20, f18, f22, 0.5f, 1);   //   += aa
    // layer 2 (stacked idx 0=ab, 1=ba, 2=aa)
    combine_w_kernel<<<cb64, 64>>>(CW + 5 * HH, Wu2 + 0 * H * 512, 256, Ws2 + 0 * HH, 256, 1.f, 0);
    combine_w_kernel<<<cb64, 64>>>(CW + 6 * HH, Wu2 + 1 * H * 512, 256, Ws2 + 1 * HH, 256, 1.f, 0);
    combine_w_kernel<<<cb64, 64>>>(CW + 7 * HH, Wu2 + 2 * H * 512, 256, Ws2 + 2 * HH, 256, 1.f, 0);
    combine_w_kernel<<<cb64, 64>>>(CW + 8 * HH, Wu2 + 0 * H * 512, 0, Wd2 + 0 * HH, 256, 1.f, 0);
    combine_w_kernel<<<cb64, 64>>>(CW + 9 * HH, Wu2 + 1 * H * 512, 0, Wd2 + 1 * HH, 256, 0.5f, 0);
    combine_w_kernel<<<cb64, 64>>>(CW + 9 * HH, Wu2 + 2 * H * 512, 0, Wd2 + 2 * HH, 256, 0.5f, 1);
    combine_b_kernel<<<1, 256>>>(BIAS + 2 * H, Wu2 + 0 * H * 512, bd2 + 0 * H, bs2 + 0 * H, bu2 + 0 * H, 1.f, 0);
    combine_b_kernel<<<1, 256>>>(BIAS + 3 * H, Wu2 + 1 * H * 512, bd2 + 1 * H, bs2 + 1 * H, bu2 + 1 * H, 0.5f, 0);
    combine_b_kernel<<<1, 256>>>(BIAS + 3 * H, Wu2 + 2 * H * 512, bd2 + 2 * H, bs2 + 2 * H, bu2 + 2 * H, 0.5f, 1);

    dim3 gemmGrid((Nn + 127) / 128, 2);
    int n4 = Nn * 64;
    int gApply = (n4 + 255) / 256;

    // ---- layer 1 ----
    sgemm_nt<<<gemmGrid, 256>>>(xA, CW + 0 * HH, nullptr, P0, Nn, 256);
    sgemm_nt<<<gemmGrid, 256>>>(xB, CW + 1 * HH, nullptr, P1, Nn, 128);
    sgemm_nt<<<gemmGrid, 256>>>(xA, CW + 2 * HH, nullptr, P2, Nn, 256);
    sgemm_nt<<<gemmGrid, 256>>>(xB, CW + 3 * HH, BIAS + 0 * H, ACCB, Nn, 128);
    sgemm_nt<<<gemmGrid, 256>>>(xA, CW + 4 * HH, BIAS + 1 * H, ACCA, Nn, 256);
    gather_kernel<<<Nn, 64>>>(ACCB, P0, ROWPTR + 0 * (NMAX + 1), COL + 0 * EMAX, 1.0f);
    gather_kernel<<<Nn, 64>>>(ACCA, P1, ROWPTR + 1 * (NMAX + 1), COL + 1 * EMAX, 0.5f);
    gather_kernel<<<Nn, 64>>>(ACCA, P2, ROWPTR + 2 * (NMAX + 1), COL + 2 * EMAX, 0.5f);
    zero_float_kernel<<<4, 256>>>(BNSUM, 1024);
    bn_stats_kernel<<<512, 256>>>(ACCA, Nn, BNSUM);
    bn_stats_kernel<<<512, 256>>>(ACCB, Nn, BNSUM + 512);
    bn_pre_kernel<<<1, 256>>>(BNSUM, bn_g + 0, bn_b + 0, BNSS, Nn);
    bn_pre_kernel<<<1, 256>>>(BNSUM + 512, bn_g + 256, bn_b + 256, BNSS + 512, Nn);
    bn_apply_kernel<<<gApply, 256>>>(ACCA, BNSS, HA, n4);
    bn_apply_kernel<<<gApply, 256>>>(ACCB, BNSS + 512, HB, n4);

    // ---- layer 2 ----
    float* outA = (float*)d_out;
    float* outB = (float*)d_out + (size_t)Nn * 256;
    sgemm_nt<<<gemmGrid, 256>>>(HA, CW + 5 * HH, nullptr, P0, Nn, 256);
    sgemm_nt<<<gemmGrid, 256>>>(HB, CW + 6 * HH, nullptr, P1, Nn, 256);
    sgemm_nt<<<gemmGrid, 256>>>(HA, CW + 7 * HH, nullptr, P2, Nn, 256);
    sgemm_nt<<<gemmGrid, 256>>>(HB, CW + 8 * HH, BIAS + 2 * H, ACCB, Nn, 256);
    sgemm_nt<<<gemmGrid, 256>>>(HA, CW + 9 * HH, BIAS + 3 * H, ACCA, Nn, 256);
    gather_kernel<<<Nn, 64>>>(ACCB, P0, ROWPTR + 0 * (NMAX + 1), COL + 0 * EMAX, 1.0f);
    gather_kernel<<<Nn, 64>>>(ACCA, P1, ROWPTR + 1 * (NMAX + 1), COL + 1 * EMAX, 0.5f);
    gather_kernel<<<Nn, 64>>>(ACCA, P2, ROWPTR + 2 * (NMAX + 1), COL + 2 * EMAX, 0.5f);
    zero_float_kernel<<<4, 256>>>(BNSUM, 1024);
    bn_stats_kernel<<<512, 256>>>(ACCA, Nn, BNSUM);
    bn_stats_kernel<<<512, 256>>>(ACCB, Nn, BNSUM + 512);
    bn_pre_kernel<<<1, 256>>>(BNSUM, bn_g + 512, bn_b + 512, BNSS, Nn);
    bn_pre_kernel<<<1, 256>>>(BNSUM + 512, bn_g + 768, bn_b + 768, BNSS + 512, Nn);
    bn_apply_kernel<<<gApply, 256>>>(ACCA, BNSS, outA, n4);
    bn_apply_kernel<<<gApply, 256>>>(ACCB, BNSS + 512, outB, n4);
}

// round 4
// speedup vs baseline: 1.2450x; 1.2450x over previous
#include <cuda_runtime.h>
#include <cuda_bf16.h>
#include <cstddef>
#include <cstdint>

#define NMAX 50048
#define EMAX 800000
#define H 256
#define HH (H*H)

// ---------------- scratch (static device globals; no allocation) ----------------
__device__ __align__(16) float g_P0[(size_t)NMAX*H];
__device__ __align__(16) float g_P1[(size_t)NMAX*H];
__device__ __align__(16) float g_P2[(size_t)NMAX*H];
__device__ __align__(16) float g_ACCA[(size_t)NMAX*H];
__device__ __align__(16) float g_ACCB[(size_t)NMAX*H];

// bf16 split-precision operand buffers: [M, 3K] layout (hi | hi | lo) for A-side
__device__ __align__(16) __nv_bfloat16 g_AextA[(size_t)NMAX*768];
__device__ __align__(16) __nv_bfloat16 g_AextB[(size_t)NMAX*768];
// weights: [256, 3K] (hi | lo | hi), 10 slots at fixed stride 256*768
__device__ __align__(16) __nv_bfloat16 g_CWext[10][(size_t)256*768];

__device__ int g_cnt[3][NMAX];
__device__ int g_rowptr[3][NMAX+1];
__device__ int g_cursor[3][NMAX];
__device__ int g_col[3][EMAX];

// fp32 combined weights (pre-split)
__device__ __align__(16) float g_CW[10][HH];
__device__ __align__(16) float g_bias[4][H];
__device__ __align__(16) float g_bnsum[1024];
__device__ __align__(16) float g_bnss[1024];

// ---------------- tiny utility kernels ----------------
__global__ void zero_int_kernel(int* p, int n) {
    int i = blockIdx.x * blockDim.x + threadIdx.x;
    if (i < n) p[i] = 0;
}
__global__ void zero_float_kernel(float* p, int n) {
    int i = blockIdx.x * blockDim.x + threadIdx.x;
    if (i < n) p[i] = 0.f;
}
__global__ void copy_int_kernel(int* dst, const int* src, int n) {
    int i = blockIdx.x * blockDim.x + threadIdx.x;
    if (i < n) dst[i] = src[i];
}

// ---------------- CSR build ----------------
__global__ void count_kernel(const int* __restrict__ dst, int E, int* __restrict__ cnt) {
    int e = blockIdx.x * blockDim.x + threadIdx.x;
    if (e < E) atomicAdd(&cnt[dst[e]], 1);
}

__global__ void scan_kernel(const int* __restrict__ cnt, int* __restrict__ rowptr, int n) {
    __shared__ int buf[1024];
    __shared__ int carry;
    int t = threadIdx.x;
    if (t == 0) carry = 0;
    __syncthreads();
    for (int base = 0; base < n; base += 1024) {
        int i = base + t;
        int v = (i < n) ? cnt[i] : 0;
        buf[t] = v;
        __syncthreads();
        for (int off = 1; off < 1024; off <<= 1) {
            int add = (t >= off) ? buf[t - off] : 0;
            __syncthreads();
            buf[t] += add;
            __syncthreads();
        }
        int incl = buf[t];
        int c = carry;
        if (i < n) rowptr[i] = c + incl - v;  // exclusive
        __syncthreads();
        if (t == 1023) carry = c + buf[1023];
        __syncthreads();
    }
    if (t == 0) rowptr[n] = carry;
}

__global__ void fill_kernel(const int* __restrict__ src, const int* __restrict__ dst,
                            int E, int* __restrict__ cur, int* __restrict__ col) {
    int e = blockIdx.x * blockDim.x + threadIdx.x;
    if (e < E) {
        int p = atomicAdd(&cur[dst[e]], 1);
        col[p] = src[e];
    }
}

// ---------------- combined-weight precompute (fp32) ----------------
__global__ void combine_w_kernel(float* __restrict__ C, const float* __restrict__ Wupd, int colOff,
                                 const float* __restrict__ W, int D, float scale, int accum) {
    int d4 = blockIdx.x * blockDim.x + threadIdx.x;
    int h = blockIdx.y;
    if (d4 >= D / 4) return;
    const float* wrow = Wupd + (size_t)h * 512 + colOff;
    float4 acc = make_float4(0.f, 0.f, 0.f, 0.f);
#pragma unroll 8
    for (int j = 0; j < 256; j++) {
        float u = wrow[j];
        float4 w = *(const float4*)(W + (size_t)j * D + d4 * 4);
        acc.x += u * w.x; acc.y += u * w.y; acc.z += u * w.z; acc.w += u * w.w;
    }
    float4* out = (float4*)(C + (size_t)h * D) + d4;
    float4 r;
    if (accum) {
        r = *out;
        r.x += scale * acc.x; r.y += scale * acc.y; r.z += scale * acc.z; r.w += scale * acc.w;
    } else {
        r.x = scale * acc.x; r.y = scale * acc.y; r.z = scale * acc.z; r.w = scale * acc.w;
    }
    *out = r;
}

__global__ void combine_b_kernel(float* __restrict__ out, const float* __restrict__ Wupd,
                                 const float* __restrict__ bdst, const float* __restrict__ bsrc,
                                 const float* __restrict__ bupd, float scale, int accum) {
    int h = threadIdx.x;
    const float* r = Wupd + (size_t)h * 512;
    float acc = bupd[h];
#pragma unroll 8
    for (int j = 0; j < 256; j++) acc += r[j] * bdst[j] + r[256 + j] * bsrc[j];
    float v = scale * acc;
    if (accum) out[h] += v; else out[h] = v;
}

// ---------------- fp32 -> split bf16 (hi at 0, hi at off_hi2, lo at off_lo) ----------------
// A-side order: off_hi2 = K, off_lo = 2K.  B-side (weights): off_hi2 = 2K, off_lo = K.
__global__ void split_kernel(const float* __restrict__ X, __nv_bfloat16* __restrict__ Y,
                             long total, int K, int off_hi2, int off_lo) {
    long i = ((long)blockIdx.x * blockDim.x + threadIdx.x) * 2;
    if (i >= total) return;
    float2 x = *(const float2*)(X + i);
    __nv_bfloat16 h0 = __float2bfloat16(x.x);
    __nv_bfloat16 h1 = __float2bfloat16(x.y);
    __nv_bfloat16 l0 = __float2bfloat16(x.x - __bfloat162float(h0));
    __nv_bfloat16 l1 = __float2bfloat16(x.y - __bfloat162float(h1));
    long row = i / K;
    int col = (int)(i % K);
    size_t base = (size_t)row * (3 * (size_t)K) + col;
    __nv_bfloat162 h = __halves2bfloat162(h0, h1);
    __nv_bfloat162 l = __halves2bfloat162(l0, l1);
    *(__nv_bfloat162*)(Y + base) = h;
    *(__nv_bfloat162*)(Y + base + off_hi2) = h;
    *(__nv_bfloat162*)(Y + base + off_lo) = l;
}

// ---------------- bf16 tensor-core GEMM: C[M,256] = Aext[M,Kext] @ Bext[256,Kext]^T ----------------
#define SKP 72  // padded smem stride (bf16)

__device__ __forceinline__ uint32_t sptr(const void* p) {
    return (uint32_t)__cvta_generic_to_shared(p);
}

__global__ __launch_bounds__(256, 2) void hgemm_nt(
    const __nv_bfloat16* __restrict__ A, const __nv_bfloat16* __restrict__ B,
    const float* __restrict__ bias, float* __restrict__ C, int M, int Kext) {
    __shared__ __nv_bfloat16 As[128][SKP];
    __shared__ __nv_bfloat16 Bs[128][SKP];
    int tid = threadIdx.x;
    int lane = tid & 31;
    int wid = tid >> 5;
    int m0 = blockIdx.x * 128;
    int n0 = blockIdx.y * 128;
    int wm = (wid >> 2) * 64;  // warp row offset within tile (0/64)
    int wn = (wid & 3) * 32;   // warp col offset (0..96)

    float acc[4][4][4];
#pragma unroll
    for (int i = 0; i < 4; i++)
#pragma unroll
        for (int j = 0; j < 4; j++)
#pragma unroll
            for (int k = 0; k < 4; k++) acc[i][j][k] = 0.f;

    // global->smem: each thread owns half a row (32 bf16 = 4 uint4) per chunk
    int lrow = tid >> 1;
    int lcolb = (tid & 1) * 32;  // bf16 col offset
    int arow = m0 + lrow; if (arow >= M) arow = M - 1;  // clamp (garbage rows never stored)

    for (int k0 = 0; k0 < Kext; k0 += 64) {
        const uint4* ga = (const uint4*)(A + (size_t)arow * Kext + k0 + lcolb);
        const uint4* gb = (const uint4*)(B + (size_t)(n0 + lrow) * Kext + k0 + lcolb);
        uint4* sa = (uint4*)&As[lrow][lcolb];
        uint4* sb = (uint4*)&Bs[lrow][lcolb];
#pragma unroll
        for (int i = 0; i < 4; i++) sa[i] = ga[i];
#pragma unroll
        for (int i = 0; i < 4; i++) sb[i] = gb[i];
        __syncthreads();

#pragma unroll
        for (int kk = 0; kk < 64; kk += 16) {
            uint32_t a[4][4];
#pragma unroll
            for (int mi = 0; mi < 4; mi++) {
                int r = wm + mi * 16 + (lane & 15);
                int c = kk + ((lane >> 4) << 3);
                uint32_t addr = sptr(&As[r][c]);
                asm volatile("ldmatrix.sync.aligned.m8n8.x4.shared.b16 {%0,%1,%2,%3}, [%4];"
                             : "=r"(a[mi][0]), "=r"(a[mi][1]), "=r"(a[mi][2]), "=r"(a[mi][3])
                             : "r"(addr));
            }
            uint32_t b[4][2];
#pragma unroll
            for (int bi = 0; bi < 2; bi++) {
                int r = wn + bi * 16 + ((lane >> 4) << 3) + (lane & 7);
                int c = kk + (((lane >> 3) & 1) << 3);
                uint32_t addr = sptr(&Bs[r][c]);
                asm volatile("ldmatrix.sync.aligned.m8n8.x4.shared.b16 {%0,%1,%2,%3}, [%4];"
                             : "=r"(b[bi * 2][0]), "=r"(b[bi * 2][1]),
                               "=r"(b[bi * 2 + 1][0]), "=r"(b[bi * 2 + 1][1])
                             : "r"(addr));
            }
#pragma unroll
            for (int mi = 0; mi < 4; mi++)
#pragma unroll
                for (int ni = 0; ni < 4; ni++) {
                    asm volatile(
                        "mma.sync.aligned.m16n8k16.row.col.f32.bf16.bf16.f32 "
                        "{%0,%1,%2,%3}, {%4,%5,%6,%7}, {%8,%9}, {%0,%1,%2,%3};"
                        : "+f"(acc[mi][ni][0]), "+f"(acc[mi][ni][1]),
                          "+f"(acc[mi][ni][2]), "+f"(acc[mi][ni][3])
                        : "r"(a[mi][0]), "r"(a[mi][1]), "r"(a[mi][2]), "r"(a[mi][3]),
                          "r"(b[ni][0]), "r"(b[ni][1]));
                }
        }
        __syncthreads();
    }

    int quad = lane >> 2;
    int tq = lane & 3;
#pragma unroll
    for (int ni = 0; ni < 4; ni++) {
        int col = n0 + wn + ni * 8 + tq * 2;
        float bv0 = bias ? bias[col] : 0.f;
        float bv1 = bias ? bias[col + 1] : 0.f;
#pragma unroll
        for (int mi = 0; mi < 4; mi++) {
            int row = m0 + wm + mi * 16 + quad;
            if (row < M) {
                float2 v = make_float2(acc[mi][ni][0] + bv0, acc[mi][ni][1] + bv1);
                *(float2*)(C + (size_t)row * 256 + col) = v;
            }
            if (row + 8 < M) {
                float2 v = make_float2(acc[mi][ni][2] + bv0, acc[mi][ni][3] + bv1);
                *(float2*)(C + (size_t)(row + 8) * 256 + col) = v;
            }
        }
    }
}

// ---------------- CSR gather-mean ----------------
__global__ void gather_kernel(float* __restrict__ acc, const float* __restrict__ P,
                              const int* __restrict__ rowptr, const int* __restrict__ col, float coef) {
    int node = blockIdx.x;
    int start = rowptr[node];
    int end = rowptr[node + 1];
    int deg = end - start;
    if (deg == 0) return;
    int t = threadIdx.x;
    float4 s = make_float4(0.f, 0.f, 0.f, 0.f);
    int e = start;
    for (; e + 4 <= end; e += 4) {
        int s0 = col[e], s1 = col[e + 1], s2 = col[e + 2], s3 = col[e + 3];
        float4 v0 = ((const float4*)(P + (size_t)s0 * 256))[t];
        float4 v1 = ((const float4*)(P + (size_t)s1 * 256))[t];
        float4 v2 = ((const float4*)(P + (size_t)s2 * 256))[t];
        float4 v3 = ((const float4*)(P + (size_t)s3 * 256))[t];
        s.x += v0.x + v1.x + v2.x + v3.x;
        s.y += v0.y + v1.y + v2.y + v3.y;
        s.z += v0.z + v1.z + v2.z + v3.z;
        s.w += v0.w + v1.w + v2.w + v3.w;
    }
    for (; e < end; e++) {
        int si = col[e];
        float4 v = ((const float4*)(P + (size_t)si * 256))[t];
        s.x += v.x; s.y += v.y; s.z += v.z; s.w += v.w;
    }
    float scale = coef / (float)deg;
    float4* o = ((float4*)(acc + (size_t)node * 256)) + t;
    float4 cur = *o;
    cur.x += scale * s.x; cur.y += scale * s.y; cur.z += scale * s.z; cur.w += scale * s.w;
    *o = cur;
}

// ---------------- BatchNorm (training stats) ----------------
__global__ void bn_stats_kernel(const float* __restrict__ X, int nrows, float* __restrict__ sums) {
    int t = threadIdx.x;
    float s = 0.f, q = 0.f;
    for (int r = blockIdx.x; r < nrows; r += gridDim.x) {
        float v = X[(size_t)r * 256 + t];
        s += v;
        q += v * v;
    }
    atomicAdd(&sums[t], s);
    atomicAdd(&sums[256 + t], q);
}

__global__ void bn_pre_kernel(const float* __restrict__ sums, const float* __restrict__ g,
                              const float* __restrict__ b, float* __restrict__ ss, int n) {
    int t = threadIdx.x;
    float fn = (float)n;
    float mean = sums[t] / fn;
    float var = sums[256 + t] / fn - mean * mean;
    float inv = rsqrtf(var + 1e-5f);
    float sc = g[t] * inv;
    ss[t] = sc;
    ss[256 + t] = b[t] - mean * sc;
}

// bn+leaky -> fp32 (final layer output)
__global__ void bn_apply_kernel(const float* __restrict__ X, const float* __restrict__ ss,
                                float* __restrict__ Y, int n4) {
    int i = blockIdx.x * blockDim.x + threadIdx.x;
    if (i >= n4) return;
    float4 x = ((const float4*)X)[i];
    int t4 = i & 63;
    float4 sc = ((const float4*)ss)[t4];
    float4 sh = ((const float4*)ss)[64 + t4];
    float4 y;
    y.x = x.x * sc.x + sh.x; y.x = y.x > 0.f ? y.x : 0.01f * y.x;
    y.y = x.y * sc.y + sh.y; y.y = y.y > 0.f ? y.y : 0.01f * y.y;
    y.z = x.z * sc.z + sh.z; y.z = y.z > 0.f ? y.z : 0.01f * y.z;
    y.w = x.w * sc.w + sh.w; y.w = y.w > 0.f ? y.w : 0.01f * y.w;
    ((float4*)Y)[i] = y;
}

// bn+leaky -> split bf16 ext (A-order: hi@0, hi@256, lo@512), row stride 768
__global__ void bn_apply_split_kernel(const float* __restrict__ X, const float* __restrict__ ss,
                                      __nv_bfloat16* __restrict__ Y, int n4) {
    int i = blockIdx.x * blockDim.x + threadIdx.x;
    if (i >= n4) return;
    float4 x = ((const float4*)X)[i];
    int t4 = i & 63;
    float4 sc = ((const float4*)ss)[t4];
    float4 sh = ((const float4*)ss)[64 + t4];
    float y0 = x.x * sc.x + sh.x; y0 = y0 > 0.f ? y0 : 0.01f * y0;
    float y1 = x.y * sc.y + sh.y; y1 = y1 > 0.f ? y1 : 0.01f * y1;
    float y2 = x.z * sc.z + sh.z; y2 = y2 > 0.f ? y2 : 0.01f * y2;
    float y3 = x.w * sc.w + sh.w; y3 = y3 > 0.f ? y3 : 0.01f * y3;
    __nv_bfloat16 h0 = __float2bfloat16(y0), h1 = __float2bfloat16(y1);
    __nv_bfloat16 h2 = __float2bfloat16(y2), h3 = __float2bfloat16(y3);
    __nv_bfloat16 l0 = __float2bfloat16(y0 - __bfloat162float(h0));
    __nv_bfloat16 l1 = __float2bfloat16(y1 - __bfloat162float(h1));
    __nv_bfloat16 l2 = __float2bfloat16(y2 - __bfloat162float(h2));
    __nv_bfloat16 l3 = __float2bfloat16(y3 - __bfloat162float(h3));
    size_t row = (size_t)(i >> 6);
    size_t base = row * 768 + (size_t)t4 * 4;
    __nv_bfloat162 ha = __halves2bfloat162(h0, h1), hb = __halves2bfloat162(h2, h3);
    __nv_bfloat162 la = __halves2bfloat162(l0, l1), lb = __halves2bfloat162(l2, l3);
    *(__nv_bfloat162*)(Y + base) = ha;       *(__nv_bfloat162*)(Y + base + 2) = hb;
    *(__nv_bfloat162*)(Y + base + 256) = ha; *(__nv_bfloat162*)(Y + base + 258) = hb;
    *(__nv_bfloat162*)(Y + base + 512) = la; *(__nv_bfloat162*)(Y + base + 514) = lb;
}

// ---------------- launcher ----------------
extern "C" void kernel_launch(void* const* d_in, const int* in_sizes, int n_in,
                              void* d_out, int out_size) {
    const float* xA = (const float*)d_in[0];
    const float* xB = (const float*)d_in[1];
    const int* eAB = (const int*)d_in[2];
    const int* eBA = (const int*)d_in[3];
    const int* eAA = (const int*)d_in[4];
    const float* bn_g = (const float*)d_in[29];
    const float* bn_b = (const float*)d_in[30];
    int Nn = in_sizes[0] / 256;
    int E = in_sizes[2] / 2;

    float *P0, *P1, *P2, *ACCA, *ACCB, *CW, *BIAS, *BNSUM, *BNSS;
    __nv_bfloat16 *AEA, *AEB, *CWE;
    int *CNT, *ROWPTR, *CURSOR, *COL;
    cudaGetSymbolAddress((void**)&P0, g_P0);
    cudaGetSymbolAddress((void**)&P1, g_P1);
    cudaGetSymbolAddress((void**)&P2, g_P2);
    cudaGetSymbolAddress((void**)&ACCA, g_ACCA);
    cudaGetSymbolAddress((void**)&ACCB, g_ACCB);
    cudaGetSymbolAddress((void**)&CW, g_CW);
    cudaGetSymbolAddress((void**)&BIAS, g_bias);
    cudaGetSymbolAddress((void**)&BNSUM, g_bnsum);
    cudaGetSymbolAddress((void**)&BNSS, g_bnss);
    cudaGetSymbolAddress((void**)&CNT, g_cnt);
    cudaGetSymbolAddress((void**)&ROWPTR, g_rowptr);
    cudaGetSymbolAddress((void**)&CURSOR, g_cursor);
    cudaGetSymbolAddress((void**)&COL, g_col);
    cudaGetSymbolAddress((void**)&AEA, g_AextA);
    cudaGetSymbolAddress((void**)&AEB, g_AextB);
    cudaGetSymbolAddress((void**)&CWE, g_CWext);
    const size_t CWS = (size_t)256 * 768;  // weight ext stride

    // ---- CSR build ----
    const int* edges[3] = {eAB, eBA, eAA};
    int gN = (Nn + 255) / 256;
    int gE = (E + 255) / 256;
    for (int ty = 0; ty < 3; ty++) {
        int* cnt = CNT + ty * NMAX;
        int* rp = ROWPTR + ty * (NMAX + 1);
        int* cur = CURSOR + ty * NMAX;
        int* col = COL + ty * EMAX;
        const int* src = edges[ty];
        const int* dst = edges[ty] + E;
        zero_int_kernel<<<gN, 256>>>(cnt, Nn);
        count_kernel<<<gE, 256>>>(dst, E, cnt);
        scan_kernel<<<1, 1024>>>(cnt, rp, Nn);
        copy_int_kernel<<<gN, 256>>>(cur, rp, Nn);
        fill_kernel<<<gE, 256>>>(src, dst, E, cur, col);
    }

    // ---- combined weights (fp32) ----
    const float* f5 = (const float*)d_in[5];   const float* f6 = (const float*)d_in[6];
    const float* f7 = (const float*)d_in[7];   const float* f8 = (const float*)d_in[8];
    const float* f9 = (const float*)d_in[9];   const float* f10 = (const float*)d_in[10];
    const float* f11 = (const float*)d_in[11]; const float* f12 = (const float*)d_in[12];
    const float* f13 = (const float*)d_in[13]; const float* f14 = (const float*)d_in[14];
    const float* f15 = (const float*)d_in[15]; const float* f16 = (const float*)d_in[16];
    const float* f17 = (const float*)d_in[17]; const float* f18 = (const float*)d_in[18];
    const float* f19 = (const float*)d_in[19]; const float* f20 = (const float*)d_in[20];
    const float* f21 = (const float*)d_in[21]; const float* f22 = (const float*)d_in[22];
    const float* Ws2 = (const float*)d_in[23]; const float* bs2 = (const float*)d_in[24];
    const float* Wd2 = (const float*)d_in[25]; const float* bd2 = (const float*)d_in[26];
    const float* Wu2 = (const float*)d_in[27]; const float* bu2 = (const float*)d_in[28];

    dim3 cb(1, 256);
    combine_w_kernel<<<cb, 64>>>(CW + 0 * HH, f9, 256, f5, 256, 1.f, 0);     // CSRC_AB1
    combine_w_kernel<<<cb, 32>>>(CW + 1 * HH, f15, 256, f11, 128, 1.f, 0);   // CSRC_BA1
    combine_w_kernel<<<cb, 64>>>(CW + 2 * HH, f21, 256, f17, 256, 1.f, 0);   // CSRC_AA1
    combine_w_kernel<<<cb, 32>>>(CW + 3 * HH, f9, 0, f7, 128, 1.f, 0);       // CDST_B1
    combine_w_kernel<<<cb, 64>>>(CW + 4 * HH, f15, 0, f13, 256, 0.5f, 0);    // CDST_A1 (ba)
    combine_w_kernel<<<cb, 64>>>(CW + 4 * HH, f21, 0, f19, 256, 0.5f, 1);    //   += aa
    combine_b_kernel<<<1, 256>>>(BIAS + 0 * H, f9, f8, f6, f10, 1.f, 0);
    combine_b_kernel<<<1, 256>>>(BIAS + 1 * H, f15, f14, f12, f16, 0.5f, 0);
    combine_b_kernel<<<1, 256>>>(BIAS + 1 * H, f21, f20, f18, f22, 0.5f, 1);
    combine_w_kernel<<<cb, 64>>>(CW + 5 * HH, Wu2 + 0 * H * 512, 256, Ws2 + 0 * HH, 256, 1.f, 0);
    combine_w_kernel<<<cb, 64>>>(CW + 6 * HH, Wu2 + 1 * H * 512, 256, Ws2 + 1 * HH, 256, 1.f, 0);
    combine_w_kernel<<<cb, 64>>>(CW + 7 * HH, Wu2 + 2 * H * 512, 256, Ws2 + 2 * HH, 256, 1.f, 0);
    combine_w_kernel<<<cb, 64>>>(CW + 8 * HH, Wu2 + 0 * H * 512, 0, Wd2 + 0 * HH, 256, 1.f, 0);
    combine_w_kernel<<<cb, 64>>>(CW + 9 * HH, Wu2 + 1 * H * 512, 0, Wd2 + 1 * HH, 256, 0.5f, 0);
    combine_w_kernel<<<cb, 64>>>(CW + 9 * HH, Wu2 + 2 * H * 512, 0, Wd2 + 2 * HH, 256, 0.5f, 1);
    combine_b_kernel<<<1, 256>>>(BIAS + 2 * H, Wu2 + 0 * H * 512, bd2 + 0 * H, bs2 + 0 * H, bu2 + 0 * H, 1.f, 0);
    combine_b_kernel<<<1, 256>>>(BIAS + 3 * H, Wu2 + 1 * H * 512, bd2 + 1 * H, bs2 + 1 * H, bu2 + 1 * H, 0.5f, 0);
    combine_b_kernel<<<1, 256>>>(BIAS + 3 * H, Wu2 + 2 * H * 512, bd2 + 2 * H, bs2 + 2 * H, bu2 + 2 * H, 0.5f, 1);

    // ---- split weights to bf16 ext (B-order: hi@0, lo@K, hi@2K) ----
    const int wK[10] = {256, 128, 256, 128, 256, 256, 256, 256, 256, 256};
    for (int k = 0; k < 10; k++) {
        long tot = 256L * wK[k];
        int g = (int)((tot / 2 + 255) / 256);
        split_kernel<<<g, 256>>>(CW + k * HH, CWE + k * CWS, tot, wK[k], 2 * wK[k], wK[k]);
    }
    // split xA / xB to bf16 ext (A-order: hi@0, hi@K, lo@2K)
    {
        long totA = (long)Nn * 256;
        long totB = (long)Nn * 128;
        split_kernel<<<(int)((totA / 2 + 255) / 256), 256>>>(xA, AEA, totA, 256, 256, 512);
        split_kernel<<<(int)((totB / 2 + 255) / 256), 256>>>(xB, AEB, totB, 128, 128, 256);
    }

    dim3 gemmGrid((Nn + 127) / 128, 2);
    int n4 = Nn * 64;
    int gApply = (n4 + 255) / 256;

    // ---- layer 1 ----
    hgemm_nt<<<gemmGrid, 256>>>(AEA, CWE + 0 * CWS, nullptr, P0, Nn, 768);
    hgemm_nt<<<gemmGrid, 256>>>(AEB, CWE + 1 * CWS, nullptr, P1, Nn, 384);
    hgemm_nt<<<gemmGrid, 256>>>(AEA, CWE + 2 * CWS, nullptr, P2, Nn, 768);
    hgemm_nt<<<gemmGrid, 256>>>(AEB, CWE + 3 * CWS, BIAS + 0 * H, ACCB, Nn, 384);
    hgemm_nt<<<gemmGrid, 256>>>(AEA, CWE + 4 * CWS, BIAS + 1 * H, ACCA, Nn, 768);
    gather_kernel<<<Nn, 64>>>(ACCB, P0, ROWPTR + 0 * (NMAX + 1), COL + 0 * EMAX, 1.0f);
    gather_kernel<<<Nn, 64>>>(ACCA, P1, ROWPTR + 1 * (NMAX + 1), COL + 1 * EMAX, 0.5f);
    gather_kernel<<<Nn, 64>>>(ACCA, P2, ROWPTR + 2 * (NMAX + 1), COL + 2 * EMAX, 0.5f);
    zero_float_kernel<<<4, 256>>>(BNSUM, 1024);
    bn_stats_kernel<<<512, 256>>>(ACCA, Nn, BNSUM);
    bn_stats_kernel<<<512, 256>>>(ACCB, Nn, BNSUM + 512);
    bn_pre_kernel<<<1, 256>>>(BNSUM, bn_g + 0, bn_b + 0, BNSS, Nn);
    bn_pre_kernel<<<1, 256>>>(BNSUM + 512, bn_g + 256, bn_b + 256, BNSS + 512, Nn);
    bn_apply_split_kernel<<<gApply, 256>>>(ACCA, BNSS, AEA, n4);
    bn_apply_split_kernel<<<gApply, 256>>>(ACCB, BNSS + 512, AEB, n4);

    // ---- layer 2 ----
    float* outA = (float*)d_out;
    float* outB = (float*)d_out + (size_t)Nn * 256;
    hgemm_nt<<<gemmGrid, 256>>>(AEA, CWE + 5 * CWS, nullptr, P0, Nn, 768);
    hgemm_nt<<<gemmGrid, 256>>>(AEB, CWE + 6 * CWS, nullptr, P1, Nn, 768);
    hgemm_nt<<<gemmGrid, 256>>>(AEA, CWE + 7 * CWS, nullptr, P2, Nn, 768);
    hgemm_nt<<<gemmGrid, 256>>>(AEB, CWE + 8 * CWS, BIAS + 2 * H, ACCB, Nn, 768);
    hgemm_nt<<<gemmGrid, 256>>>(AEA, CWE + 9 * CWS, BIAS + 3 * H, ACCA, Nn, 768);
    gather_kernel<<<Nn, 64>>>(ACCB, P0, ROWPTR + 0 * (NMAX + 1), COL + 0 * EMAX, 1.0f);
    gather_kernel<<<Nn, 64>>>(ACCA, P1, ROWPTR + 1 * (NMAX + 1), COL + 1 * EMAX, 0.5f);
    gather_kernel<<<Nn, 64>>>(ACCA, P2, ROWPTR + 2 * (NMAX + 1), COL + 2 * EMAX, 0.5f);
    zero_float_kernel<<<4, 256>>>(BNSUM, 1024);
    bn_stats_kernel<<<512, 256>>>(ACCA, Nn, BNSUM);
    bn_stats_kernel<<<512, 256>>>(ACCB, Nn, BNSUM + 512);
    bn_pre_kernel<<<1, 256>>>(BNSUM, bn_g + 512, bn_b + 512, BNSS, Nn);
    bn_pre_kernel<<<1, 256>>>(BNSUM + 512, bn_g + 768, bn_b + 768, BNSS + 512, Nn);
    bn_apply_kernel<<<gApply, 256>>>(ACCA, BNSS, outA, n4);
    bn_apply_kernel<<<gApply, 256>>>(ACCB, BNSS + 512, outB, n4);
}

// round 7
// speedup vs baseline: 1.3629x; 1.0947x over previous
#include <cuda_runtime.h>
#include <cuda_bf16.h>
#include <cstddef>
#include <cstdint>

#define NMAX 50048
#define EMAX 800000
#define H 256
#define HH (H*H)
#define SK2 40  // padded smem row stride (bf16) for 32-wide K chunks

// ---------------- scratch (static device globals; no allocation) ----------------
__device__ __align__(16) float g_P0[(size_t)NMAX*H];
__device__ __align__(16) float g_P1[(size_t)NMAX*H];
__device__ __align__(16) float g_P2[(size_t)NMAX*H];
__device__ __align__(16) float g_ACCA[(size_t)NMAX*H];
__device__ __align__(16) float g_ACCB[(size_t)NMAX*H];

__device__ __align__(16) __nv_bfloat16 g_AextA[(size_t)NMAX*768];
__device__ __align__(16) __nv_bfloat16 g_AextB[(size_t)NMAX*768];
__device__ __align__(16) __nv_bfloat16 g_CWext[10][(size_t)256*768];

__device__ int g_cnt[3][NMAX];
__device__ int g_rowptr[3][NMAX+1];
__device__ int g_cursor[3][NMAX];
__device__ int g_col[3][EMAX];

__device__ __align__(16) float g_CW[10][HH];
__device__ __align__(16) float g_bias[4][H];
__device__ __align__(16) float g_bnsum[1024];
__device__ __align__(16) float g_bnss[1024];

// ---------------- tiny utility kernels ----------------
__global__ void zero_int_kernel(int* p, int n) {
    int i = blockIdx.x * blockDim.x + threadIdx.x;
    if (i < n) p[i] = 0;
}
__global__ void zero_float_kernel(float* p, int n) {
    int i = blockIdx.x * blockDim.x + threadIdx.x;
    if (i < n) p[i] = 0.f;
}
__global__ void copy_int_kernel(int* dst, const int* src, int n) {
    int i = blockIdx.x * blockDim.x + threadIdx.x;
    if (i < n) dst[i] = src[i];
}

// ---------------- CSR build ----------------
__global__ void count_kernel(const int* __restrict__ dst, int E, int* __restrict__ cnt) {
    int e = blockIdx.x * blockDim.x + threadIdx.x;
    if (e < E) atomicAdd(&cnt[dst[e]], 1);
}

__global__ void scan_kernel(const int* __restrict__ cnt, int* __restrict__ rowptr, int n) {
    __shared__ int wsums[32];
    __shared__ int carry;
    int t = threadIdx.x, lane = t & 31, warp = t >> 5;
    if (t == 0) carry = 0;
    __syncthreads();
    for (int base = 0; base < n; base += 1024) {
        int i = base + t;
        int v = (i < n) ? cnt[i] : 0;
        int x = v;
#pragma unroll
        for (int off = 1; off < 32; off <<= 1) {
            int y = __shfl_up_sync(0xFFFFFFFFu, x, off);
            if (lane >= off) x += y;
        }
        if (lane == 31) wsums[warp] = x;
        __syncthreads();
        if (warp == 0) {
            int s = wsums[lane];
#pragma unroll
            for (int off = 1; off < 32; off <<= 1) {
                int y = __shfl_up_sync(0xFFFFFFFFu, s, off);
                if (lane >= off) s += y;
            }
            wsums[lane] = s;
        }
        __syncthreads();
        int woff = (warp == 0) ? 0 : wsums[warp - 1];
        int excl = carry + woff + x - v;
        if (i < n) rowptr[i] = excl;
        int total = wsums[31];
        __syncthreads();
        if (t == 0) carry += total;
        __syncthreads();
    }
    if (t == 0) rowptr[n] = carry;
}

__global__ void fill_kernel(const int* __restrict__ src, const int* __restrict__ dst,
                            int E, int* __restrict__ cur, int* __restrict__ col) {
    int e = blockIdx.x * blockDim.x + threadIdx.x;
    if (e < E) {
        int p = atomicAdd(&cur[dst[e]], 1);
        col[p] = src[e];
    }
}

// ---------------- combined-weight precompute (fp32) ----------------
__global__ void combine_w_kernel(float* __restrict__ C, const float* __restrict__ Wupd, int colOff,
                                 const float* __restrict__ W, int D, float scale, int accum) {
    int d4 = blockIdx.x * blockDim.x + threadIdx.x;
    int h = blockIdx.y;
    if (d4 >= D / 4) return;
    const float* wrow = Wupd + (size_t)h * 512 + colOff;
    float4 acc = make_float4(0.f, 0.f, 0.f, 0.f);
#pragma unroll 8
    for (int j = 0; j < 256; j++) {
        float u = wrow[j];
        float4 w = *(const float4*)(W + (size_t)j * D + d4 * 4);
        acc.x += u * w.x; acc.y += u * w.y; acc.z += u * w.z; acc.w += u * w.w;
    }
    float4* out = (float4*)(C + (size_t)h * D) + d4;
    float4 r;
    if (accum) {
        r = *out;
        r.x += scale * acc.x; r.y += scale * acc.y; r.z += scale * acc.z; r.w += scale * acc.w;
    } else {
        r.x = scale * acc.x; r.y = scale * acc.y; r.z = scale * acc.z; r.w = scale * acc.w;
    }
    *out = r;
}

__global__ void combine_b_kernel(float* __restrict__ out, const float* __restrict__ Wupd,
                                 const float* __restrict__ bdst, const float* __restrict__ bsrc,
                                 const float* __restrict__ bupd, float scale, int accum) {
    int h = threadIdx.x;
    const float* r = Wupd + (size_t)h * 512;
    float acc = bupd[h];
#pragma unroll 8
    for (int j = 0; j < 256; j++) acc += r[j] * bdst[j] + r[256 + j] * bsrc[j];
    float v = scale * acc;
    if (accum) out[h] += v; else out[h] = v;
}

// ---------------- fp32 -> split bf16 ----------------
// A-side order: off_hi2 = K, off_lo = 2K.  B-side (weights): off_hi2 = 2K, off_lo = K.
__global__ void split_kernel(const float* __restrict__ X, __nv_bfloat16* __restrict__ Y,
                             long total, int K, int off_hi2, int off_lo) {
    long i = ((long)blockIdx.x * blockDim.x + threadIdx.x) * 2;
    if (i >= total) return;
    float2 x = *(const float2*)(X + i);
    __nv_bfloat16 h0 = __float2bfloat16(x.x);
    __nv_bfloat16 h1 = __float2bfloat16(x.y);
    __nv_bfloat16 l0 = __float2bfloat16(x.x - __bfloat162float(h0));
    __nv_bfloat16 l1 = __float2bfloat16(x.y - __bfloat162float(h1));
    long row = i / K;
    int col = (int)(i % K);
    size_t base = (size_t)row * (3 * (size_t)K) + col;
    __nv_bfloat162 h = __halves2bfloat162(h0, h1);
    __nv_bfloat162 l = __halves2bfloat162(l0, l1);
    *(__nv_bfloat162*)(Y + base) = h;
    *(__nv_bfloat162*)(Y + base + off_hi2) = h;
    *(__nv_bfloat162*)(Y + base + off_lo) = l;
}

// ---------------- pipelined bf16 TC GEMM (static smem, 32-wide K), fused N ----------------
// grid.x = N/128 (n-fast for A-tile L2 reuse), grid.y = ceil(M/128).
__device__ __forceinline__ uint32_t sptr(const void* p) {
    return (uint32_t)__cvta_generic_to_shared(p);
}

__global__ __launch_bounds__(256) void hgemm_fused(
    const __nv_bfloat16* __restrict__ A,
    const __nv_bfloat16* __restrict__ W0, const __nv_bfloat16* __restrict__ W1,
    const __nv_bfloat16* __restrict__ W2,
    const float* __restrict__ b0, const float* __restrict__ b1, const float* __restrict__ b2,
    float* __restrict__ C0, float* __restrict__ C1, float* __restrict__ C2,
    int M, int Kext) {
    __shared__ __nv_bfloat16 As[2][128][SK2];
    __shared__ __nv_bfloat16 Bs[2][128][SK2];

    int tid = threadIdx.x;
    int lane = tid & 31;
    int wid = tid >> 5;
    int m0 = blockIdx.y * 128;
    int idx = blockIdx.x >> 1;
    int nn0 = (blockIdx.x & 1) * 128;
    const __nv_bfloat16* W = (idx == 0) ? W0 : (idx == 1) ? W1 : W2;
    const float* bias = (idx == 0) ? b0 : (idx == 1) ? b1 : b2;
    float* C = (idx == 0) ? C0 : (idx == 1) ? C1 : C2;

    int wm = (wid >> 2) * 64;
    int wn = (wid & 3) * 32;

    float acc[4][4][4];
#pragma unroll
    for (int i = 0; i < 4; i++)
#pragma unroll
        for (int j = 0; j < 4; j++)
#pragma unroll
            for (int k = 0; k < 4; k++) acc[i][j][k] = 0.f;

    // loads: each thread owns half a 32-bf16 row (16 bf16 = 32B = 2x16B cp.async)
    int lrow = tid >> 1;
    int lcolb = (tid & 1) * 16;
    int arow = m0 + lrow; if (arow >= M) arow = M - 1;  // clamp; garbage rows never stored
    const __nv_bfloat16* gA = A + (size_t)arow * Kext + lcolb;
    const __nv_bfloat16* gB = W + (size_t)(nn0 + lrow) * Kext + lcolb;

    int niter = Kext >> 5;

#define LD_STAGE(s, k0)                                                              \
    do {                                                                             \
        uint32_t sa = sptr(&As[(s)][lrow][lcolb]);                                   \
        uint32_t sb = sptr(&Bs[(s)][lrow][lcolb]);                                   \
        const __nv_bfloat16* pa = gA + (k0);                                         \
        const __nv_bfloat16* pb = gB + (k0);                                         \
        asm volatile("cp.async.cg.shared.global [%0], [%1], 16;\n" ::                \
                     "r"(sa), "l"(pa));                                              \
        asm volatile("cp.async.cg.shared.global [%0], [%1], 16;\n" ::                \
                     "r"(sa + 16), "l"(pa + 8));                                     \
        asm volatile("cp.async.cg.shared.global [%0], [%1], 16;\n" ::                \
                     "r"(sb), "l"(pb));                                              \
        asm volatile("cp.async.cg.shared.global [%0], [%1], 16;\n" ::                \
                     "r"(sb + 16), "l"(pb + 8));                                     \
        asm volatile("cp.async.commit_group;\n" ::: "memory");                       \
    } while (0)

    LD_STAGE(0, 0);

    for (int it = 0; it < niter; it++) {
        int cur = it & 1;
        asm volatile("cp.async.wait_group 0;\n" ::: "memory");
        __syncthreads();
        if (it + 1 < niter) LD_STAGE((it + 1) & 1, (it + 1) << 5);

#pragma unroll
        for (int kk = 0; kk < 32; kk += 16) {
            uint32_t a[4][4];
#pragma unroll
            for (int mi = 0; mi < 4; mi++) {
                int r = wm + mi * 16 + (lane & 15);
                int c = kk + ((lane >> 4) << 3);
                uint32_t addr = sptr(&As[cur][r][c]);
                asm volatile("ldmatrix.sync.aligned.m8n8.x4.shared.b16 {%0,%1,%2,%3}, [%4];"
                             : "=r"(a[mi][0]), "=r"(a[mi][1]), "=r"(a[mi][2]), "=r"(a[mi][3])
                             : "r"(addr));
            }
            uint32_t b[4][2];
#pragma unroll
            for (int bi = 0; bi < 2; bi++) {
                int r = wn + bi * 16 + ((lane >> 4) << 3) + (lane & 7);
                int c = kk + (((lane >> 3) & 1) << 3);
                uint32_t addr = sptr(&Bs[cur][r][c]);
                asm volatile("ldmatrix.sync.aligned.m8n8.x4.shared.b16 {%0,%1,%2,%3}, [%4];"
                             : "=r"(b[bi * 2][0]), "=r"(b[bi * 2][1]),
                               "=r"(b[bi * 2 + 1][0]), "=r"(b[bi * 2 + 1][1])
                             : "r"(addr));
            }
#pragma unroll
            for (int mi = 0; mi < 4; mi++)
#pragma unroll
                for (int ni = 0; ni < 4; ni++) {
                    asm volatile(
                        "mma.sync.aligned.m16n8k16.row.col.f32.bf16.bf16.f32 "
                        "{%0,%1,%2,%3}, {%4,%5,%6,%7}, {%8,%9}, {%0,%1,%2,%3};"
                        : "+f"(acc[mi][ni][0]), "+f"(acc[mi][ni][1]),
                          "+f"(acc[mi][ni][2]), "+f"(acc[mi][ni][3])
                        : "r"(a[mi][0]), "r"(a[mi][1]), "r"(a[mi][2]), "r"(a[mi][3]),
                          "r"(b[ni][0]), "r"(b[ni][1]));
                }
        }
        __syncthreads();
    }
#undef LD_STAGE

    int quad = lane >> 2;
    int tq = lane & 3;
#pragma unroll
    for (int ni = 0; ni < 4; ni++) {
        int col = nn0 + wn + ni * 8 + tq * 2;
        float bv0 = bias ? bias[col] : 0.f;
        float bv1 = bias ? bias[col + 1] : 0.f;
#pragma unroll
        for (int mi = 0; mi < 4; mi++) {
            int row = m0 + wm + mi * 16 + quad;
            if (row < M) {
                float2 v = make_float2(acc[mi][ni][0] + bv0, acc[mi][ni][1] + bv1);
                *(float2*)(C + (size_t)row * 256 + col) = v;
            }
            if (row + 8 < M) {
                float2 v = make_float2(acc[mi][ni][2] + bv0, acc[mi][ni][3] + bv1);
                *(float2*)(C + (size_t)(row + 8) * 256 + col) = v;
            }
        }
    }
}

// ---------------- CSR gather-mean ----------------
__device__ __forceinline__ float4 row_sum(const float* __restrict__ P,
                                          const int* __restrict__ col,
                                          int start, int end, int t) {
    float4 s = make_float4(0.f, 0.f, 0.f, 0.f);
    int e = start;
    for (; e + 4 <= end; e += 4) {
        int s0 = col[e], s1 = col[e + 1], s2 = col[e + 2], s3 = col[e + 3];
        float4 v0 = ((const float4*)(P + (size_t)s0 * 256))[t];
        float4 v1 = ((const float4*)(P + (size_t)s1 * 256))[t];
        float4 v2 = ((const float4*)(P + (size_t)s2 * 256))[t];
        float4 v3 = ((const float4*)(P + (size_t)s3 * 256))[t];
        s.x += v0.x + v1.x + v2.x + v3.x;
        s.y += v0.y + v1.y + v2.y + v3.y;
        s.z += v0.z + v1.z + v2.z + v3.z;
        s.w += v0.w + v1.w + v2.w + v3.w;
    }
    for (; e < end; e++) {
        int si = col[e];
        float4 v = ((const float4*)(P + (size_t)si * 256))[t];
        s.x += v.x; s.y += v.y; s.z += v.z; s.w += v.w;
    }
    return s;
}

__global__ void gather_kernel(float* __restrict__ acc, const float* __restrict__ P,
                              const int* __restrict__ rowptr, const int* __restrict__ col) {
    int node = blockIdx.x;
    int start = rowptr[node];
    int end = rowptr[node + 1];
    int deg = end - start;
    if (deg == 0) return;
    int t = threadIdx.x;
    float4 s = row_sum(P, col, start, end, t);
    float scale = 1.0f / (float)deg;
    float4* o = ((float4*)(acc + (size_t)node * 256)) + t;
    float4 cur = *o;
    cur.x += scale * s.x; cur.y += scale * s.y; cur.z += scale * s.z; cur.w += scale * s.w;
    *o = cur;
}

__global__ void gather2_kernel(float* __restrict__ acc,
                               const float* __restrict__ Pa, const int* __restrict__ rpa,
                               const int* __restrict__ cola,
                               const float* __restrict__ Pb, const int* __restrict__ rpb,
                               const int* __restrict__ colb) {
    int node = blockIdx.x;
    int t = threadIdx.x;
    int sa0 = rpa[node], sa1 = rpa[node + 1];
    int sb0 = rpb[node], sb1 = rpb[node + 1];
    int dega = sa1 - sa0, degb = sb1 - sb0;
    if (dega == 0 && degb == 0) return;
    float4 add = make_float4(0.f, 0.f, 0.f, 0.f);
    if (dega > 0) {
        float4 s = row_sum(Pa, cola, sa0, sa1, t);
        float sc = 0.5f / (float)dega;
        add.x += sc * s.x; add.y += sc * s.y; add.z += sc * s.z; add.w += sc * s.w;
    }
    if (degb > 0) {
        float4 s = row_sum(Pb, colb, sb0, sb1, t);
        float sc = 0.5f / (float)degb;
        add.x += sc * s.x; add.y += sc * s.y; add.z += sc * s.z; add.w += sc * s.w;
    }
    float4* o = ((float4*)(acc + (size_t)node * 256)) + t;
    float4 cur = *o;
    cur.x += add.x; cur.y += add.y; cur.z += add.z; cur.w += add.w;
    *o = cur;
}

// ---------------- BatchNorm (training stats) ----------------
__global__ void bn_stats_kernel(const float* __restrict__ X, int nrows, float* __restrict__ sums) {
    int t = threadIdx.x;
    float s = 0.f, q = 0.f;
    for (int r = blockIdx.x; r < nrows; r += gridDim.x) {
        float v = X[(size_t)r * 256 + t];
        s += v;
        q += v * v;
    }
    atomicAdd(&sums[t], s);
    atomicAdd(&sums[256 + t], q);
}

__global__ void bn_pre_kernel(const float* __restrict__ sums, const float* __restrict__ g,
                              const float* __restrict__ b, float* __restrict__ ss, int n) {
    int t = threadIdx.x;
    float fn = (float)n;
    float mean = sums[t] / fn;
    float var = sums[256 + t] / fn - mean * mean;
    float inv = rsqrtf(var + 1e-5f);
    float sc = g[t] * inv;
    ss[t] = sc;
    ss[256 + t] = b[t] - mean * sc;
}

__global__ void bn_apply_kernel(const float* __restrict__ X, const float* __restrict__ ss,
                                float* __restrict__ Y, int n4) {
    int i = blockIdx.x * blockDim.x + threadIdx.x;
    if (i >= n4) return;
    float4 x = ((const float4*)X)[i];
    int t4 = i & 63;
    float4 sc = ((const float4*)ss)[t4];
    float4 sh = ((const float4*)ss)[64 + t4];
    float4 y;
    y.x = x.x * sc.x + sh.x; y.x = y.x > 0.f ? y.x : 0.01f * y.x;
    y.y = x.y * sc.y + sh.y; y.y = y.y > 0.f ? y.y : 0.01f * y.y;
    y.z = x.z * sc.z + sh.z; y.z = y.z > 0.f ? y.z : 0.01f * y.z;
    y.w = x.w * sc.w + sh.w; y.w = y.w > 0.f ? y.w : 0.01f * y.w;
    ((float4*)Y)[i] = y;
}

__global__ void bn_apply_split_kernel(const float* __restrict__ X, const float* __restrict__ ss,
                                      __nv_bfloat16* __restrict__ Y, int n4) {
    int i = blockIdx.x * blockDim.x + threadIdx.x;
    if (i >= n4) return;
    float4 x = ((const float4*)X)[i];
    int t4 = i & 63;
    float4 sc = ((const float4*)ss)[t4];
    float4 sh = ((const float4*)ss)[64 + t4];
    float y0 = x.x * sc.x + sh.x; y0 = y0 > 0.f ? y0 : 0.01f * y0;
    float y1 = x.y * sc.y + sh.y; y1 = y1 > 0.f ? y1 : 0.01f * y1;
    float y2 = x.z * sc.z + sh.z; y2 = y2 > 0.f ? y2 : 0.01f * y2;
    float y3 = x.w * sc.w + sh.w; y3 = y3 > 0.f ? y3 : 0.01f * y3;
    __nv_bfloat16 h0 = __float2bfloat16(y0), h1 = __float2bfloat16(y1);
    __nv_bfloat16 h2 = __float2bfloat16(y2), h3 = __float2bfloat16(y3);
    __nv_bfloat16 l0 = __float2bfloat16(y0 - __bfloat162float(h0));
    __nv_bfloat16 l1 = __float2bfloat16(y1 - __bfloat162float(h1));
    __nv_bfloat16 l2 = __float2bfloat16(y2 - __bfloat162float(h2));
    __nv_bfloat16 l3 = __float2bfloat16(y3 - __bfloat162float(h3));
    size_t row = (size_t)(i >> 6);
    size_t base = row * 768 + (size_t)t4 * 4;
    __nv_bfloat162 ha = __halves2bfloat162(h0, h1), hb = __halves2bfloat162(h2, h3);
    __nv_bfloat162 la = __halves2bfloat162(l0, l1), lb = __halves2bfloat162(l2, l3);
    *(__nv_bfloat162*)(Y + base) = ha;       *(__nv_bfloat162*)(Y + base + 2) = hb;
    *(__nv_bfloat162*)(Y + base + 256) = ha; *(__nv_bfloat162*)(Y + base + 258) = hb;
    *(__nv_bfloat162*)(Y + base + 512) = la; *(__nv_bfloat162*)(Y + base + 514) = lb;
}

// ---------------- launcher ----------------
extern "C" void kernel_launch(void* const* d_in, const int* in_sizes, int n_in,
                              void* d_out, int out_size) {
    const float* xA = (const float*)d_in[0];
    const float* xB = (const float*)d_in[1];
    const int* eAB = (const int*)d_in[2];
    const int* eBA = (const int*)d_in[3];
    const int* eAA = (const int*)d_in[4];
    const float* bn_g = (const float*)d_in[29];
    const float* bn_b = (const float*)d_in[30];
    int Nn = in_sizes[0] / 256;
    int E = in_sizes[2] / 2;

    float *P0, *P1, *P2, *ACCA, *ACCB, *CW, *BIAS, *BNSUM, *BNSS;
    __nv_bfloat16 *AEA, *AEB, *CWE;
    int *CNT, *ROWPTR, *CURSOR, *COL;
    cudaGetSymbolAddress((void**)&P0, g_P0);
    cudaGetSymbolAddress((void**)&P1, g_P1);
    cudaGetSymbolAddress((void**)&P2, g_P2);
    cudaGetSymbolAddress((void**)&ACCA, g_ACCA);
    cudaGetSymbolAddress((void**)&ACCB, g_ACCB);
    cudaGetSymbolAddress((void**)&CW, g_CW);
    cudaGetSymbolAddress((void**)&BIAS, g_bias);
    cudaGetSymbolAddress((void**)&BNSUM, g_bnsum);
    cudaGetSymbolAddress((void**)&BNSS, g_bnss);
    cudaGetSymbolAddress((void**)&CNT, g_cnt);
    cudaGetSymbolAddress((void**)&ROWPTR, g_rowptr);
    cudaGetSymbolAddress((void**)&CURSOR, g_cursor);
    cudaGetSymbolAddress((void**)&COL, g_col);
    cudaGetSymbolAddress((void**)&AEA, g_AextA);
    cudaGetSymbolAddress((void**)&AEB, g_AextB);
    cudaGetSymbolAddress((void**)&CWE, g_CWext);
    const size_t CWS = (size_t)256 * 768;

    // ---- CSR build ----
    const int* edges[3] = {eAB, eBA, eAA};
    int gN = (Nn + 255) / 256;
    int gE = (E + 255) / 256;
    for (int ty = 0; ty < 3; ty++) {
        int* cnt = CNT + ty * NMAX;
        int* rp = ROWPTR + ty * (NMAX + 1);
        int* cur = CURSOR + ty * NMAX;
        int* col = COL + ty * EMAX;
        const int* src = edges[ty];
        const int* dst = edges[ty] + E;
        zero_int_kernel<<<gN, 256>>>(cnt, Nn);
        count_kernel<<<gE, 256>>>(dst, E, cnt);
        scan_kernel<<<1, 1024>>>(cnt, rp, Nn);
        copy_int_kernel<<<gN, 256>>>(cur, rp, Nn);
        fill_kernel<<<gE, 256>>>(src, dst, E, cur, col);
    }

    // ---- combined weights (fp32) ----
    const float* f5 = (const float*)d_in[5];   const float* f6 = (const float*)d_in[6];
    const float* f7 = (const float*)d_in[7];   const float* f8 = (const float*)d_in[8];
    const float* f9 = (const float*)d_in[9];   const float* f10 = (const float*)d_in[10];
    const float* f11 = (const float*)d_in[11]; const float* f12 = (const float*)d_in[12];
    const float* f13 = (const float*)d_in[13]; const float* f14 = (const float*)d_in[14];
    const float* f15 = (const float*)d_in[15]; const float* f16 = (const float*)d_in[16];
    const float* f17 = (const float*)d_in[17]; const float* f18 = (const float*)d_in[18];
    const float* f19 = (const float*)d_in[19]; const float* f20 = (const float*)d_in[20];
    const float* f21 = (const float*)d_in[21]; const float* f22 = (const float*)d_in[22];
    const float* Ws2 = (const float*)d_in[23]; const float* bs2 = (const float*)d_in[24];
    const float* Wd2 = (const float*)d_in[25]; const float* bd2 = (const float*)d_in[26];
    const float* Wu2 = (const float*)d_in[27]; const float* bu2 = (const float*)d_in[28];

    dim3 cb(1, 256);
    combine_w_kernel<<<cb, 64>>>(CW + 0 * HH, f9, 256, f5, 256, 1.f, 0);     // CSRC_AB1
    combine_w_kernel<<<cb, 32>>>(CW + 1 * HH, f15, 256, f11, 128, 1.f, 0);   // CSRC_BA1
    combine_w_kernel<<<cb, 64>>>(CW + 2 * HH, f21, 256, f17, 256, 1.f, 0);   // CSRC_AA1
    combine_w_kernel<<<cb, 32>>>(CW + 3 * HH, f9, 0, f7, 128, 1.f, 0);       // CDST_B1
    combine_w_kernel<<<cb, 64>>>(CW + 4 * HH, f15, 0, f13, 256, 0.5f, 0);    // CDST_A1 (ba)
    combine_w_kernel<<<cb, 64>>>(CW + 4 * HH, f21, 0, f19, 256, 0.5f, 1);    //   += aa
    combine_b_kernel<<<1, 256>>>(BIAS + 0 * H, f9, f8, f6, f10, 1.f, 0);
    combine_b_kernel<<<1, 256>>>(BIAS + 1 * H, f15, f14, f12, f16, 0.5f, 0);
    combine_b_kernel<<<1, 256>>>(BIAS + 1 * H, f21, f20, f18, f22, 0.5f, 1);
    combine_w_kernel<<<cb, 64>>>(CW + 5 * HH, Wu2 + 0 * H * 512, 256, Ws2 + 0 * HH, 256, 1.f, 0);
    combine_w_kernel<<<cb, 64>>>(CW + 6 * HH, Wu2 + 1 * H * 512, 256, Ws2 + 1 * HH, 256, 1.f, 0);
    combine_w_kernel<<<cb, 64>>>(CW + 7 * HH, Wu2 + 2 * H * 512, 256, Ws2 + 2 * HH, 256, 1.f, 0);
    combine_w_kernel<<<cb, 64>>>(CW + 8 * HH, Wu2 + 0 * H * 512, 0, Wd2 + 0 * HH, 256, 1.f, 0);
    combine_w_kernel<<<cb, 64>>>(CW + 9 * HH, Wu2 + 1 * H * 512, 0, Wd2 + 1 * HH, 256, 0.5f, 0);
    combine_w_kernel<<<cb, 64>>>(CW + 9 * HH, Wu2 + 2 * H * 512, 0, Wd2 + 2 * HH, 256, 0.5f, 1);
    combine_b_kernel<<<1, 256>>>(BIAS + 2 * H, Wu2 + 0 * H * 512, bd2 + 0 * H, bs2 + 0 * H, bu2 + 0 * H, 1.f, 0);
    combine_b_kernel<<<1, 256>>>(BIAS + 3 * H, Wu2 + 1 * H * 512, bd2 + 1 * H, bs2 + 1 * H, bu2 + 1 * H, 0.5f, 0);
    combine_b_kernel<<<1, 256>>>(BIAS + 3 * H, Wu2 + 2 * H * 512, bd2 + 2 * H, bs2 + 2 * H, bu2 + 2 * H, 0.5f, 1);

    // ---- split weights to bf16 ext (B-order: hi@0, lo@K, hi@2K) ----
    const int wK[10] = {256, 128, 256, 128, 256, 256, 256, 256, 256, 256};
    for (int k = 0; k < 10; k++) {
        long tot = 256L * wK[k];
        int g = (int)((tot / 2 + 255) / 256);
        split_kernel<<<g, 256>>>(CW + k * HH, CWE + k * CWS, tot, wK[k], 2 * wK[k], wK[k]);
    }
    // split xA / xB to bf16 ext (A-order: hi@0, hi@K, lo@2K)
    {
        long totA = (long)Nn * 256;
        long totB = (long)Nn * 128;
        split_kernel<<<(int)((totA / 2 + 255) / 256), 256>>>(xA, AEA, totA, 256, 256, 512);
        split_kernel<<<(int)((totB / 2 + 255) / 256), 256>>>(xB, AEB, totB, 128, 128, 256);
    }

    int mblocks = (Nn + 127) / 128;
    dim3 gridA(6, mblocks);  // N=768: slots {P0, P2, ACCA}
    dim3 gridB(4, mblocks);  // N=512: slots {P1, ACCB}
    int n4 = Nn * 64;
    int gApply = (n4 + 255) / 256;

    const int* RP0 = ROWPTR + 0 * (NMAX + 1); const int* CL0 = COL + 0 * EMAX;
    const int* RP1 = ROWPTR + 1 * (NMAX + 1); const int* CL1 = COL + 1 * EMAX;
    const int* RP2 = ROWPTR + 2 * (NMAX + 1); const int* CL2 = COL + 2 * EMAX;

    // ---- layer 1 ----
    hgemm_fused<<<gridA, 256>>>(AEA, CWE + 0 * CWS, CWE + 2 * CWS, CWE + 4 * CWS,
                                nullptr, nullptr, BIAS + 1 * H,
                                P0, P2, ACCA, Nn, 768);
    hgemm_fused<<<gridB, 256>>>(AEB, CWE + 1 * CWS, CWE + 3 * CWS, nullptr,
                                nullptr, BIAS + 0 * H, nullptr,
                                P1, ACCB, nullptr, Nn, 384);
    gather_kernel<<<Nn, 64>>>(ACCB, P0, RP0, CL0);
    gather2_kernel<<<Nn, 64>>>(ACCA, P1, RP1, CL1, P2, RP2, CL2);
    zero_float_kernel<<<4, 256>>>(BNSUM, 1024);
    bn_stats_kernel<<<512, 256>>>(ACCA, Nn, BNSUM);
    bn_stats_kernel<<<512, 256>>>(ACCB, Nn, BNSUM + 512);
    bn_pre_kernel<<<1, 256>>>(BNSUM, bn_g + 0, bn_b + 0, BNSS, Nn);
    bn_pre_kernel<<<1, 256>>>(BNSUM + 512, bn_g + 256, bn_b + 256, BNSS + 512, Nn);
    bn_apply_split_kernel<<<gApply, 256>>>(ACCA, BNSS, AEA, n4);
    bn_apply_split_kernel<<<gApply, 256>>>(ACCB, BNSS + 512, AEB, n4);

    // ---- layer 2 ----
    float* outA = (float*)d_out;
    float* outB = (float*)d_out + (size_t)Nn * 256;
    hgemm_fused<<<gridA, 256>>>(AEA, CWE + 5 * CWS, CWE + 7 * CWS, CWE + 9 * CWS,
                                nullptr, nullptr, BIAS + 3 * H,
                                P0, P2, ACCA, Nn, 768);
    hgemm_fused<<<gridB, 256>>>(AEB, CWE + 6 * CWS, CWE + 8 * CWS, nullptr,
                                nullptr, BIAS + 2 * H, nullptr,
                                P1, ACCB, nullptr, Nn, 768);
    gather_kernel<<<Nn, 64>>>(ACCB, P0, RP0, CL0);
    gather2_kernel<<<Nn, 64>>>(ACCA, P1, RP1, CL1, P2, RP2, CL2);
    zero_float_kernel<<<4, 256>>>(BNSUM, 1024);
    bn_stats_kernel<<<512, 256>>>(ACCA, Nn, BNSUM);
    bn_stats_kernel<<<512, 256>>>(ACCB, Nn, BNSUM + 512);
    bn_pre_kernel<<<1, 256>>>(BNSUM, bn_g + 512, bn_b + 512, BNSS, Nn);
    bn_pre_kernel<<<1, 256>>>(BNSUM + 512, bn_g + 768, bn_b + 768, BNSS + 512, Nn);
    bn_apply_kernel<<<gApply, 256>>>(ACCA, BNSS, outA, n4);
    bn_apply_kernel<<<gApply, 256>>>(ACCB, BNSS + 512, outB, n4);
}

// round 10
// speedup vs baseline: 1.7655x; 1.2953x over previous
#include <cuda_runtime.h>
#include <cuda_bf16.h>
#include <cstddef>
#include <cstdint>

#define NMAX 50048
#define EMAX 800000
#define H 256
#define HH (H*H)
#define SK2 40  // padded smem row stride (bf16) for 32-wide K chunks

// ---------------- scratch (static device globals; no allocation) ----------------
__device__ __align__(16) float g_P0[(size_t)NMAX*H];
__device__ __align__(16) float g_P1[(size_t)NMAX*H];
__device__ __align__(16) float g_P2[(size_t)NMAX*H];
__device__ __align__(16) float g_ACCA[(size_t)NMAX*H];
__device__ __align__(16) float g_ACCB[(size_t)NMAX*H];

__device__ __align__(16) __nv_bfloat16 g_AextA[(size_t)NMAX*768];
__device__ __align__(16) __nv_bfloat16 g_AextB[(size_t)NMAX*768];
__device__ __align__(16) __nv_bfloat16 g_CWext[10][(size_t)256*768];

__device__ int g_cnt[3*NMAX];
__device__ int g_rowptr[3][NMAX+1];
__device__ int g_cursor[3*NMAX];
__device__ int g_col[3][EMAX];

__device__ __align__(16) float g_bias[4][H];
__device__ __align__(16) float g_bnsum[1024];
__device__ __align__(16) float g_bnss[1024];

// ---------------- fused weight-combine + bf16 split (slot config via switch) ----------------
// grid (1, 256, 10), block 64. Writes g_CWext[slot] in B-order: hi@0, lo@D, hi@2D.
__global__ void weights_fused_kernel(
    const float* f5, const float* f7, const float* f9, const float* f11,
    const float* f13, const float* f15, const float* f17, const float* f19,
    const float* f21, const float* Ws2, const float* Wd2, const float* Wu2) {
    int slot = blockIdx.z;
    int h = blockIdx.y;
    int t = threadIdx.x;
    const float *up0 = nullptr, *w0 = nullptr, *up1 = nullptr, *w1 = nullptr;
    int co0 = 0, D = 256;
    float s0 = 1.f, s1 = 0.f;
    switch (slot) {
        case 0: up0 = f9;  co0 = 256; w0 = f5;  D = 256; break;                      // CSRC_AB1
        case 1: up0 = f15; co0 = 256; w0 = f11; D = 128; break;                      // CSRC_BA1
        case 2: up0 = f21; co0 = 256; w0 = f17; D = 256; break;                      // CSRC_AA1
        case 3: up0 = f9;  co0 = 0;   w0 = f7;  D = 128; break;                      // CDST_B1
        case 4: up0 = f15; co0 = 0;   w0 = f13; s0 = 0.5f;
                up1 = f21; w1 = f19; s1 = 0.5f; break;                               // CDST_A1
        case 5: up0 = Wu2;               co0 = 256; w0 = Ws2;          break;        // CSRC_AB2
        case 6: up0 = Wu2 + 1 * H * 512; co0 = 256; w0 = Ws2 + 1 * HH; break;        // CSRC_BA2
        case 7: up0 = Wu2 + 2 * H * 512; co0 = 256; w0 = Ws2 + 2 * HH; break;        // CSRC_AA2
        case 8: up0 = Wu2;               co0 = 0;   w0 = Wd2;          break;        // CDST_B2
        case 9: up0 = Wu2 + 1 * H * 512; co0 = 0;   w0 = Wd2 + 1 * HH; s0 = 0.5f;
                up1 = Wu2 + 2 * H * 512; w1 = Wd2 + 2 * HH; s1 = 0.5f; break;        // CDST_A2
    }
    if (t * 4 >= D) return;
    float4 acc = make_float4(0.f, 0.f, 0.f, 0.f);
    {
        const float* wrow = up0 + (size_t)h * 512 + co0;
#pragma unroll 8
        for (int j = 0; j < 256; j++) {
            float u = wrow[j];
            float4 w = *(const float4*)(w0 + (size_t)j * D + t * 4);
            acc.x += u * w.x; acc.y += u * w.y; acc.z += u * w.z; acc.w += u * w.w;
        }
        acc.x *= s0; acc.y *= s0; acc.z *= s0; acc.w *= s0;
    }
    if (up1) {
        const float* wrow = up1 + (size_t)h * 512;  // co1 always 0
        float4 a2 = make_float4(0.f, 0.f, 0.f, 0.f);
#pragma unroll 8
        for (int j = 0; j < 256; j++) {
            float u = wrow[j];
            float4 w = *(const float4*)(w1 + (size_t)j * D + t * 4);
            a2.x += u * w.x; a2.y += u * w.y; a2.z += u * w.z; a2.w += u * w.w;
        }
        acc.x += s1 * a2.x; acc.y += s1 * a2.y; acc.z += s1 * a2.z; acc.w += s1 * a2.w;
    }
    __nv_bfloat16 h0 = __float2bfloat16(acc.x), h1 = __float2bfloat16(acc.y);
    __nv_bfloat16 h2 = __float2bfloat16(acc.z), h3 = __float2bfloat16(acc.w);
    __nv_bfloat16 l0 = __float2bfloat16(acc.x - __bfloat162float(h0));
    __nv_bfloat16 l1 = __float2bfloat16(acc.y - __bfloat162float(h1));
    __nv_bfloat16 l2 = __float2bfloat16(acc.z - __bfloat162float(h2));
    __nv_bfloat16 l3 = __float2bfloat16(acc.w - __bfloat162float(h3));
    __nv_bfloat162 ha = __halves2bfloat162(h0, h1), hb = __halves2bfloat162(h2, h3);
    __nv_bfloat162 la = __halves2bfloat162(l0, l1), lb = __halves2bfloat162(l2, l3);
    __nv_bfloat16* out = g_CWext[slot] + (size_t)h * 3 * D + t * 4;
    *(__nv_bfloat162*)(out) = ha;           *(__nv_bfloat162*)(out + 2) = hb;
    *(__nv_bfloat162*)(out + D) = la;       *(__nv_bfloat162*)(out + D + 2) = lb;
    *(__nv_bfloat162*)(out + 2 * D) = ha;   *(__nv_bfloat162*)(out + 2 * D + 2) = hb;
}

__device__ __forceinline__ float bias_acc(const float* Wupd, const float* bdst,
                                          const float* bsrc, const float* bupd, int t) {
    const float* r = Wupd + (size_t)t * 512;
    float acc = bupd[t];
#pragma unroll 8
    for (int j = 0; j < 256; j++) acc += r[j] * bdst[j] + r[256 + j] * bsrc[j];
    return acc;
}

// 1 block, 256 threads: all 4 combined biases -> g_bias
__global__ void bias_fused_kernel(
    const float* f9, const float* f8, const float* f6, const float* f10,
    const float* f15, const float* f14, const float* f12, const float* f16,
    const float* f21, const float* f20, const float* f18, const float* f22,
    const float* Wu2, const float* bd2, const float* bs2, const float* bu2) {
    int t = threadIdx.x;
    g_bias[0][t] = bias_acc(f9, f8, f6, f10, t);
    g_bias[1][t] = 0.5f * bias_acc(f15, f14, f12, f16, t)
                 + 0.5f * bias_acc(f21, f20, f18, f22, t);
    g_bias[2][t] = bias_acc(Wu2 + 0 * H * 512, bd2 + 0 * H, bs2 + 0 * H, bu2 + 0 * H, t);
    g_bias[3][t] = 0.5f * bias_acc(Wu2 + 1 * H * 512, bd2 + 1 * H, bs2 + 1 * H, bu2 + 1 * H, t)
                 + 0.5f * bias_acc(Wu2 + 2 * H * 512, bd2 + 2 * H, bs2 + 2 * H, bu2 + 2 * H, t);
}

// ---------------- fused fp32 -> split bf16 for xA/xB (A-order: hi@0, hi@K, lo@2K) ----------------
__global__ void splitx_kernel(const float* __restrict__ XA, const float* __restrict__ XB,
                              long totA, long totB) {
    int which = blockIdx.y;
    const float* X = which ? XB : XA;
    __nv_bfloat16* Y = which ? g_AextB : g_AextA;
    long total = which ? totB : totA;
    int K = which ? 128 : 256;
    long i = ((long)blockIdx.x * blockDim.x + threadIdx.x) * 2;
    if (i >= total) return;
    float2 x = *(const float2*)(X + i);
    __nv_bfloat16 h0 = __float2bfloat16(x.x);
    __nv_bfloat16 h1 = __float2bfloat16(x.y);
    __nv_bfloat16 l0 = __float2bfloat16(x.x - __bfloat162float(h0));
    __nv_bfloat16 l1 = __float2bfloat16(x.y - __bfloat162float(h1));
    long row = i / K;
    int col = (int)(i % K);
    size_t base = (size_t)row * (3 * (size_t)K) + col;
    __nv_bfloat162 h = __halves2bfloat162(h0, h1);
    __nv_bfloat162 l = __halves2bfloat162(l0, l1);
    *(__nv_bfloat162*)(Y + base) = h;
    *(__nv_bfloat162*)(Y + base + K) = h;
    *(__nv_bfloat162*)(Y + base + 2 * K) = l;
}

// ---------------- merged pipelined bf16 TC GEMM (all operands are device globals) ----------------
__device__ __forceinline__ uint32_t sptr(const void* p) {
    return (uint32_t)__cvta_generic_to_shared(p);
}

// grid (10, mblocks): slot = x>>1, nn0 = (x&1)*128. layer: 0 or 1.
__global__ __launch_bounds__(256) void hgemm_merged(int M, int layer) {
    __shared__ __nv_bfloat16 As[2][128][SK2];
    __shared__ __nv_bfloat16 Bs[2][128][SK2];

    int tid = threadIdx.x;
    int lane = tid & 31;
    int wid = tid >> 5;
    int m0 = blockIdx.y * 128;
    int slot = blockIdx.x >> 1;
    int nn0 = (blockIdx.x & 1) * 128;

    bool useB = (slot == 1) || (slot == 3);
    const __nv_bfloat16* A = useB ? g_AextB : g_AextA;
    const __nv_bfloat16* W = g_CWext[layer * 5 + slot];
    int Kext = (layer == 0 && useB) ? 384 : 768;
    float* C = (slot == 0) ? g_P0 : (slot == 1) ? g_P1 : (slot == 2) ? g_P2
             : (slot == 3) ? g_ACCB : g_ACCA;
    const float* bias = (slot == 3) ? g_bias[layer ? 2 : 0]
                      : (slot == 4) ? g_bias[layer ? 3 : 1] : nullptr;

    int wm = (wid >> 2) * 64;
    int wn = (wid & 3) * 32;

    float acc[4][4][4];
#pragma unroll
    for (int i = 0; i < 4; i++)
#pragma unroll
        for (int j = 0; j < 4; j++)
#pragma unroll
            for (int k = 0; k < 4; k++) acc[i][j][k] = 0.f;

    int lrow = tid >> 1;
    int lcolb = (tid & 1) * 16;
    int arow = m0 + lrow; if (arow >= M) arow = M - 1;  // clamp; garbage rows never stored
    const __nv_bfloat16* gA = A + (size_t)arow * Kext + lcolb;
    const __nv_bfloat16* gB = W + (size_t)(nn0 + lrow) * Kext + lcolb;

    int niter = Kext >> 5;

#define LD_STAGE(s, k0)                                                              \
    do {                                                                             \
        uint32_t sa = sptr(&As[(s)][lrow][lcolb]);                                   \
        uint32_t sb = sptr(&Bs[(s)][lrow][lcolb]);                                   \
        const __nv_bfloat16* pa = gA + (k0);                                         \
        const __nv_bfloat16* pb = gB + (k0);                                         \
        asm volatile("cp.async.cg.shared.global [%0], [%1], 16;\n" ::                \
                     "r"(sa), "l"(pa));                                              \
        asm volatile("cp.async.cg.shared.global [%0], [%1], 16;\n" ::                \
                     "r"(sa + 16), "l"(pa + 8));                                     \
        asm volatile("cp.async.cg.shared.global [%0], [%1], 16;\n" ::                \
                     "r"(sb), "l"(pb));                                              \
        asm volatile("cp.async.cg.shared.global [%0], [%1], 16;\n" ::                \
                     "r"(sb + 16), "l"(pb + 8));                                     \
        asm volatile("cp.async.commit_group;\n" ::: "memory");                       \
    } while (0)

    LD_STAGE(0, 0);

    for (int it = 0; it < niter; it++) {
        int cur = it & 1;
        asm volatile("cp.async.wait_group 0;\n" ::: "memory");
        __syncthreads();
        if (it + 1 < niter) LD_STAGE((it + 1) & 1, (it + 1) << 5);

#pragma unroll
        for (int kk = 0; kk < 32; kk += 16) {
            uint32_t a[4][4];
#pragma unroll
            for (int mi = 0; mi < 4; mi++) {
                int r = wm + mi * 16 + (lane & 15);
                int c = kk + ((lane >> 4) << 3);
                uint32_t addr = sptr(&As[cur][r][c]);
                asm volatile("ldmatrix.sync.aligned.m8n8.x4.shared.b16 {%0,%1,%2,%3}, [%4];"
                             : "=r"(a[mi][0]), "=r"(a[mi][1]), "=r"(a[mi][2]), "=r"(a[mi][3])
                             : "r"(addr));
            }
            uint32_t b[4][2];
#pragma unroll
            for (int bi = 0; bi < 2; bi++) {
                int r = wn + bi * 16 + ((lane >> 4) << 3) + (lane & 7);
                int c = kk + (((lane >> 3) & 1) << 3);
                uint32_t addr = sptr(&Bs[cur][r][c]);
                asm volatile("ldmatrix.sync.aligned.m8n8.x4.shared.b16 {%0,%1,%2,%3}, [%4];"
                             : "=r"(b[bi * 2][0]), "=r"(b[bi * 2][1]),
                               "=r"(b[bi * 2 + 1][0]), "=r"(b[bi * 2 + 1][1])
                             : "r"(addr));
            }
#pragma unroll
            for (int mi = 0; mi < 4; mi++)
#pragma unroll
                for (int ni = 0; ni < 4; ni++) {
                    asm volatile(
                        "mma.sync.aligned.m16n8k16.row.col.f32.bf16.bf16.f32 "
                        "{%0,%1,%2,%3}, {%4,%5,%6,%7}, {%8,%9}, {%0,%1,%2,%3};"
                        : "+f"(acc[mi][ni][0]), "+f"(acc[mi][ni][1]),
                          "+f"(acc[mi][ni][2]), "+f"(acc[mi][ni][3])
                        : "r"(a[mi][0]), "r"(a[mi][1]), "r"(a[mi][2]), "r"(a[mi][3]),
                          "r"(b[ni][0]), "r"(b[ni][1]));
                }
        }
        __syncthreads();
    }
#undef LD_STAGE

    int quad = lane >> 2;
    int tq = lane & 3;
#pragma unroll
    for (int ni = 0; ni < 4; ni++) {
        int col = nn0 + wn + ni * 8 + tq * 2;
        float bv0 = bias ? bias[col] : 0.f;
        float bv1 = bias ? bias[col + 1] : 0.f;
#pragma unroll
        for (int mi = 0; mi < 4; mi++) {
            int row = m0 + wm + mi * 16 + quad;
            if (row < M) {
                float2 v = make_float2(acc[mi][ni][0] + bv0, acc[mi][ni][1] + bv1);
                *(float2*)(C + (size_t)row * 256 + col) = v;
            }
            if (row + 8 < M) {
                float2 v = make_float2(acc[mi][ni][2] + bv0, acc[mi][ni][3] + bv1);
                *(float2*)(C + (size_t)(row + 8) * 256 + col) = v;
            }
        }
    }
}

// ---------------- CSR build (fused across 3 edge types) ----------------
__global__ void zero3_kernel(int n) {
    int i = blockIdx.x * blockDim.x + threadIdx.x;
    if (i < n) g_cnt[i] = 0;
}

__global__ void count3_kernel(const int* __restrict__ e0, const int* __restrict__ e1,
                              const int* __restrict__ e2, int E) {
    int e = blockIdx.x * blockDim.x + threadIdx.x;
    if (e >= E) return;
    int ty = blockIdx.y;
    const int* dst = (ty == 0 ? e0 : ty == 1 ? e1 : e2) + E;
    atomicAdd(&g_cnt[ty * NMAX + dst[e]], 1);
}

// grid 3 blocks (one per type), 1024 threads; writes rowptr AND cursor copy
__global__ void scan3_kernel(int n) {
    __shared__ int wsums[32];
    __shared__ int carry;
    int ty = blockIdx.x;
    const int* c = g_cnt + ty * NMAX;
    int* rowptr = g_rowptr[ty];
    int* cursor = g_cursor + ty * NMAX;
    int t = threadIdx.x, lane = t & 31, warp = t >> 5;
    if (t == 0) carry = 0;
    __syncthreads();
    for (int base = 0; base < n; base += 1024) {
        int i = base + t;
        int v = (i < n) ? c[i] : 0;
        int x = v;
#pragma unroll
        for (int off = 1; off < 32; off <<= 1) {
            int y = __shfl_up_sync(0xFFFFFFFFu, x, off);
            if (lane >= off) x += y;
        }
        if (lane == 31) wsums[warp] = x;
        __syncthreads();
        if (warp == 0) {
            int s = wsums[lane];
#pragma unroll
            for (int off = 1; off < 32; off <<= 1) {
                int y = __shfl_up_sync(0xFFFFFFFFu, s, off);
                if (lane >= off) s += y;
            }
            wsums[lane] = s;
        }
        __syncthreads();
        int woff = (warp == 0) ? 0 : wsums[warp - 1];
        int excl = carry + woff + x - v;
        if (i < n) { rowptr[i] = excl; cursor[i] = excl; }
        int total = wsums[31];
        __syncthreads();
        if (t == 0) carry += total;
        __syncthreads();
    }
    if (t == 0) rowptr[n] = carry;
}

__global__ void fill3_kernel(const int* __restrict__ e0, const int* __restrict__ e1,
                             const int* __restrict__ e2, int E) {
    int e = blockIdx.x * blockDim.x + threadIdx.x;
    if (e >= E) return;
    int ty = blockIdx.y;
    const int* base = (ty == 0 ? e0 : ty == 1 ? e1 : e2);
    int p = atomicAdd(&g_cursor[ty * NMAX + base[E + e]], 1);
    g_col[ty][p] = base[e];
}

// ---------------- merged CSR gather-mean (both node-type tasks per layer) ----------------
__device__ __forceinline__ float4 row_sum(const float* __restrict__ P,
                                          const int* __restrict__ col,
                                          int start, int end, int t) {
    float4 s = make_float4(0.f, 0.f, 0.f, 0.f);
    int e = start;
    for (; e + 4 <= end; e += 4) {
        int s0 = col[e], s1 = col[e + 1], s2 = col[e + 2], s3 = col[e + 3];
        float4 v0 = ((const float4*)(P + (size_t)s0 * 256))[t];
        float4 v1 = ((const float4*)(P + (size_t)s1 * 256))[t];
        float4 v2 = ((const float4*)(P + (size_t)s2 * 256))[t];
        float4 v3 = ((const float4*)(P + (size_t)s3 * 256))[t];
        s.x += v0.x + v1.x + v2.x + v3.x;
        s.y += v0.y + v1.y + v2.y + v3.y;
        s.z += v0.z + v1.z + v2.z + v3.z;
        s.w += v0.w + v1.w + v2.w + v3.w;
    }
    for (; e < end; e++) {
        int si = col[e];
        float4 v = ((const float4*)(P + (size_t)si * 256))[t];
        s.x += v.x; s.y += v.y; s.z += v.z; s.w += v.w;
    }
    return s;
}

__global__ void gather_layer_kernel() {
    int node = blockIdx.x;
    int t = threadIdx.x;
    // task 1: ACCB += mean(P0 over csr0)
    {
        int s0 = g_rowptr[0][node], s1 = g_rowptr[0][node + 1];
        int deg = s1 - s0;
        if (deg > 0) {
            float4 s = row_sum(g_P0, g_col[0], s0, s1, t);
            float sc = 1.0f / (float)deg;
            float4* o = ((float4*)(g_ACCB + (size_t)node * 256)) + t;
            float4 c = *o;
            c.x += sc * s.x; c.y += sc * s.y; c.z += sc * s.z; c.w += sc * s.w;
            *o = c;
        }
    }
    // task 2: ACCA += 0.5*mean(P1 over csr1) + 0.5*mean(P2 over csr2)
    {
        int a0 = g_rowptr[1][node], a1 = g_rowptr[1][node + 1];
        int b0 = g_rowptr[2][node], b1 = g_rowptr[2][node + 1];
        int dega = a1 - a0, degb = b1 - b0;
        if (dega == 0 && degb == 0) return;
        float4 add = make_float4(0.f, 0.f, 0.f, 0.f);
        if (dega > 0) {
            float4 s = row_sum(g_P1, g_col[1], a0, a1, t);
            float sc = 0.5f / (float)dega;
            add.x += sc * s.x; add.y += sc * s.y; add.z += sc * s.z; add.w += sc * s.w;
        }
        if (degb > 0) {
            float4 s = row_sum(g_P2, g_col[2], b0, b1, t);
            float sc = 0.5f / (float)degb;
            add.x += sc * s.x; add.y += sc * s.y; add.z += sc * s.z; add.w += sc * s.w;
        }
        float4* o = ((float4*)(g_ACCA + (size_t)node * 256)) + t;
        float4 c = *o;
        c.x += add.x; c.y += add.y; c.z += add.z; c.w += add.w;
        *o = c;
    }
}

// ---------------- BatchNorm (training stats), merged A+B ----------------
__global__ void zerobn_kernel() {
    int i = blockIdx.x * blockDim.x + threadIdx.x;
    if (i < 1024) g_bnsum[i] = 0.f;
}

__global__ void bn_stats2_kernel(int nrows) {
    int t = threadIdx.x;
    const float* X = blockIdx.y ? g_ACCB : g_ACCA;
    float* out = g_bnsum + (blockIdx.y ? 512 : 0);
    float s = 0.f, q = 0.f;
    for (int r = blockIdx.x; r < nrows; r += gridDim.x) {
        float v = X[(size_t)r * 256 + t];
        s += v;
        q += v * v;
    }
    atomicAdd(&out[t], s);
    atomicAdd(&out[256 + t], q);
}

// grid (1,2): y=0 -> A stats, y=1 -> B stats
__global__ void bn_pre2_kernel(const float* __restrict__ g, const float* __restrict__ b, int n) {
    int t = threadIdx.x;
    int off = blockIdx.y * 512;
    int goff = blockIdx.y * 256;
    float fn = (float)n;
    float mean = g_bnsum[off + t] / fn;
    float var = g_bnsum[off + 256 + t] / fn - mean * mean;
    float inv = rsqrtf(var + 1e-5f);
    float sc = g[goff + t] * inv;
    g_bnss[off + t] = sc;
    g_bnss[off + 256 + t] = b[goff + t] - mean * sc;
}

// grid (gApply, 2): final bn+leaky -> fp32 out
__global__ void bn_apply2_kernel(float* __restrict__ Ya, float* __restrict__ Yb, int n4) {
    int i = blockIdx.x * blockDim.x + threadIdx.x;
    if (i >= n4) return;
    const float* X = blockIdx.y ? g_ACCB : g_ACCA;
    float* Y = blockIdx.y ? Yb : Ya;
    const float* s = g_bnss + blockIdx.y * 512;
    float4 x = ((const float4*)X)[i];
    int t4 = i & 63;
    float4 sc = ((const float4*)s)[t4];
    float4 sh = ((const float4*)s)[64 + t4];
    float4 y;
    y.x = x.x * sc.x + sh.x; y.x = y.x > 0.f ? y.x : 0.01f * y.x;
    y.y = x.y * sc.y + sh.y; y.y = y.y > 0.f ? y.y : 0.01f * y.y;
    y.z = x.z * sc.z + sh.z; y.z = y.z > 0.f ? y.z : 0.01f * y.z;
    y.w = x.w * sc.w + sh.w; y.w = y.w > 0.f ? y.w : 0.01f * y.w;
    ((float4*)Y)[i] = y;
}

// grid (gApply, 2): bn+leaky -> split bf16 ext into g_AextA/g_AextB (hi@0, hi@256, lo@512)
__global__ void bn_apply_split2_kernel(int n4) {
    int i = blockIdx.x * blockDim.x + threadIdx.x;
    if (i >= n4) return;
    const float* X = blockIdx.y ? g_ACCB : g_ACCA;
    __nv_bfloat16* Y = blockIdx.y ? g_AextB : g_AextA;
    const float* s = g_bnss + blockIdx.y * 512;
    float4 x = ((const float4*)X)[i];
    int t4 = i & 63;
    float4 sc = ((const float4*)s)[t4];
    float4 sh = ((const float4*)s)[64 + t4];
    float y0 = x.x * sc.x + sh.x; y0 = y0 > 0.f ? y0 : 0.01f * y0;
    float y1 = x.y * sc.y + sh.y; y1 = y1 > 0.f ? y1 : 0.01f * y1;
    float y2 = x.z * sc.z + sh.z; y2 = y2 > 0.f ? y2 : 0.01f * y2;
    float y3 = x.w * sc.w + sh.w; y3 = y3 > 0.f ? y3 : 0.01f * y3;
    __nv_bfloat16 h0 = __float2bfloat16(y0), h1 = __float2bfloat16(y1);
    __nv_bfloat16 h2 = __float2bfloat16(y2), h3 = __float2bfloat16(y3);
    __nv_bfloat16 l0 = __float2bfloat16(y0 - __bfloat162float(h0));
    __nv_bfloat16 l1 = __float2bfloat16(y1 - __bfloat162float(h1));
    __nv_bfloat16 l2 = __float2bfloat16(y2 - __bfloat162float(h2));
    __nv_bfloat16 l3 = __float2bfloat16(y3 - __bfloat162float(h3));
    size_t row = (size_t)(i >> 6);
    size_t base = row * 768 + (size_t)t4 * 4;
    __nv_bfloat162 ha = __halves2bfloat162(h0, h1), hb = __halves2bfloat162(h2, h3);
    __nv_bfloat162 la = __halves2bfloat162(l0, l1), lb = __halves2bfloat162(l2, l3);
    *(__nv_bfloat162*)(Y + base) = ha;       *(__nv_bfloat162*)(Y + base + 2) = hb;
    *(__nv_bfloat162*)(Y + base + 256) = ha; *(__nv_bfloat162*)(Y + base + 258) = hb;
    *(__nv_bfloat162*)(Y + base + 512) = la; *(__nv_bfloat162*)(Y + base + 514) = lb;
}

// ---------------- launcher ----------------
extern "C" void kernel_launch(void* const* d_in, const int* in_sizes, int n_in,
                              void* d_out, int out_size) {
    const float* xA = (const float*)d_in[0];
    const float* xB = (const float*)d_in[1];
    const int* eAB = (const int*)d_in[2];
    const int* eBA = (const int*)d_in[3];
    const int* eAA = (const int*)d_in[4];
    const float* bn_g = (const float*)d_in[29];
    const float* bn_b = (const float*)d_in[30];
    int Nn = in_sizes[0] / 256;
    int E = in_sizes[2] / 2;

    const float* f5 = (const float*)d_in[5];   const float* f6 = (const float*)d_in[6];
    const float* f7 = (const float*)d_in[7];   const float* f8 = (const float*)d_in[8];
    const float* f9 = (const float*)d_in[9];   const float* f10 = (const float*)d_in[10];
    const float* f11 = (const float*)d_in[11]; const float* f12 = (const float*)d_in[12];
    const float* f13 = (const float*)d_in[13]; const float* f14 = (const float*)d_in[14];
    const float* f15 = (const float*)d_in[15]; const float* f16 = (const float*)d_in[16];
    const float* f17 = (const float*)d_in[17]; const float* f18 = (const float*)d_in[18];
    const float* f19 = (const float*)d_in[19]; const float* f20 = (const float*)d_in[20];
    const float* f21 = (const float*)d_in[21]; const float* f22 = (const float*)d_in[22];
    const float* Ws2 = (const float*)d_in[23]; const float* bs2 = (const float*)d_in[24];
    const float* Wd2 = (const float*)d_in[25]; const float* bd2 = (const float*)d_in[26];
    const float* Wu2 = (const float*)d_in[27]; const float* bu2 = (const float*)d_in[28];

    // ---- [0] fused weight combine+split ----
    weights_fused_kernel<<<dim3(1, 256, 10), 64>>>(f5, f7, f9, f11, f13, f15, f17, f19,
                                                   f21, Ws2, Wd2, Wu2);
    // ---- [1] fused bias combine ----
    bias_fused_kernel<<<1, 256>>>(f9, f8, f6, f10, f15, f14, f12, f16,
                                  f21, f20, f18, f22, Wu2, bd2, bs2, bu2);
    // ---- [2] fused x split ----
    long totA = (long)Nn * 256, totB = (long)Nn * 128;
    int gSplit = (int)((totA / 2 + 255) / 256);
    splitx_kernel<<<dim3(gSplit, 2), 256>>>(xA, xB, totA, totB);

    // ---- [3] merged GEMM layer 1 (ncu -s target) ----
    int mblocks = (Nn + 127) / 128;
    hgemm_merged<<<dim3(10, mblocks), 256>>>(Nn, 0);

    // ---- [4..7] CSR build (fused across types) ----
    int gE = (E + 255) / 256;
    zero3_kernel<<<(3 * NMAX + 255) / 256, 256>>>(3 * NMAX);
    count3_kernel<<<dim3(gE, 3), 256>>>(eAB, eBA, eAA, E);
    scan3_kernel<<<3, 1024>>>(Nn);
    fill3_kernel<<<dim3(gE, 3), 256>>>(eAB, eBA, eAA, E);

    int n4 = Nn * 64;
    int gApply = (n4 + 255) / 256;

    // ---- layer 1 tail ----
    gather_layer_kernel<<<Nn, 64>>>();
    zerobn_kernel<<<4, 256>>>();
    bn_stats2_kernel<<<dim3(512, 2), 256>>>(Nn);
    bn_pre2_kernel<<<dim3(1, 2), 256>>>(bn_g + 0, bn_b + 0, Nn);
    bn_apply_split2_kernel<<<dim3(gApply, 2), 256>>>(n4);

    // ---- layer 2 ----
    hgemm_merged<<<dim3(10, mblocks), 256>>>(Nn, 1);
    gather_layer_kernel<<<Nn, 64>>>();
    zerobn_kernel<<<4, 256>>>();
    bn_stats2_kernel<<<dim3(512, 2), 256>>>(Nn);
    bn_pre2_kernel<<<dim3(1, 2), 256>>>(bn_g + 512, bn_b + 512, Nn);
    float* outA = (float*)d_out;
    float* outB = (float*)d_out + (size_t)Nn * 256;
    bn_apply2_kernel<<<dim3(gApply, 2), 256>>>(outA, outB, n4);
}